// round 1
// baseline (speedup 1.0000x reference)
#include <cuda_runtime.h>
#include <math.h>
#include <stdint.h>

#define N_TOK 65536
#define DD 32
#define NH 8
#define HDIM 256
#define BLK 256
#define NBLK 256

// ---------------- device scratch (no runtime allocation allowed) ----------------
__device__ unsigned long long g_sort[N_TOK];          // (key<<32)|idx, sorted ascending
__device__ float g_q[N_TOK * HDIM];                   // [b][h][d][i] = ((b*8+h)*8192 + d*256 + i)
__device__ float g_k[N_TOK * HDIM];
__device__ float g_v[N_TOK * HDIM];
__device__ float g_att[N_TOK * HDIM];                 // same layout
__device__ float g_p[N_TOK * 2];                      // sorted coords dims 1,2
__device__ float g_w2[NH * 2];

// ---------------- bitonic sort ----------------
// local: full bitonic network for k=2..2048 inside one 2048-element chunk
__global__ void sort_init_local(const float* __restrict__ coords) {
    __shared__ unsigned long long sh[2048];
    int tid = threadIdx.x;
    int base = blockIdx.x * 2048;
    for (int t = tid; t < 2048; t += 1024) {
        int gi = base + t;
        unsigned int key = __float_as_uint(coords[3 * gi]);   // uniform [0,1): bits monotonic
        sh[t] = ((unsigned long long)key << 32) | (unsigned int)gi;
    }
    __syncthreads();
    for (int k = 2; k <= 2048; k <<= 1) {
        for (int j = k >> 1; j > 0; j >>= 1) {
            for (int t = tid; t < 2048; t += 1024) {
                int p = t ^ j;
                if (p > t) {
                    bool up = (((base + t) & k) == 0);
                    unsigned long long a = sh[t], b = sh[p];
                    if ((a > b) == up) { sh[t] = b; sh[p] = a; }
                }
            }
            __syncthreads();
        }
    }
    for (int t = tid; t < 2048; t += 1024) g_sort[base + t] = sh[t];
}

// global compare-exchange pass for one (k, j), j >= 2048
__global__ void sort_gpass(int k, int j) {
    int t = blockIdx.x * blockDim.x + threadIdx.x;     // 32768 threads
    int l = ((t & ~(j - 1)) << 1) | (t & (j - 1));
    int p = l | j;
    bool up = ((l & k) == 0);
    unsigned long long a = g_sort[l], b = g_sort[p];
    if ((a > b) == up) { g_sort[l] = b; g_sort[p] = a; }
}

// finish a merge stage: j = 1024..1 within a 2048 chunk
__global__ void sort_lfinish(int k) {
    __shared__ unsigned long long sh[2048];
    int tid = threadIdx.x;
    int base = blockIdx.x * 2048;
    for (int t = tid; t < 2048; t += 1024) sh[t] = g_sort[base + t];
    __syncthreads();
    bool up = ((base & k) == 0);                        // k>=4096: uniform per chunk
    for (int j = 1024; j > 0; j >>= 1) {
        for (int t = tid; t < 2048; t += 1024) {
            int p = t ^ j;
            if (p > t) {
                unsigned long long a = sh[t], b = sh[p];
                if ((a > b) == up) { sh[t] = b; sh[p] = a; }
            }
        }
        __syncthreads();
    }
    for (int t = tid; t < 2048; t += 1024) g_sort[base + t] = sh[t];
}

// ---------------- RPE weight reduction: w2[h][c] = mean_{d,w} W[h,d,c,w]^2 ----------------
__global__ void calc_w2(const float* __restrict__ wrpe) {
    int t = threadIdx.x;
    if (t < 16) {
        int h = t >> 1, c = t & 1;
        float acc = 0.f;
        for (int d = 0; d < 32; d++)
            for (int w = 0; w < 8; w++) {
                float v = wrpe[(h * 32 + d) * 16 + c * 8 + w];
                acc += v * v;
            }
        g_w2[t] = acc * (1.f / 256.f);
    }
}

// ---------------- LayerNorm + QKV projection into sorted layout ----------------
__device__ __forceinline__ void do_proj(const float* __restrict__ W, float* __restrict__ dst,
                                        const float* xv, float* wsh, int tid) {
    __syncthreads();
    const float4* wsrc = (const float4*)W;
    float4* wd = (float4*)wsh;
#pragma unroll
    for (int u = 0; u < 8; u++) wd[tid + 256 * u] = wsrc[tid + 256 * u];
    __syncthreads();
#pragma unroll 4
    for (int o = 0; o < 256; o++) {
        const float4* wr4 = (const float4*)(wsh + o * 32);
        float acc = 0.f;
#pragma unroll
        for (int q8 = 0; q8 < 8; q8++) {
            float4 w4 = wr4[q8];
            acc = fmaf(xv[4 * q8 + 0], w4.x, acc);
            acc = fmaf(xv[4 * q8 + 1], w4.y, acc);
            acc = fmaf(xv[4 * q8 + 2], w4.z, acc);
            acc = fmaf(xv[4 * q8 + 3], w4.w, acc);
        }
        dst[((o >> 5) << 13) + ((o & 31) << 8)] = acc;   // [h][d][i] stride; coalesced per o
    }
}

__global__ void __launch_bounds__(256) proj_kernel(
    const float* __restrict__ x, const float* __restrict__ coords,
    const float* __restrict__ wq, const float* __restrict__ wk, const float* __restrict__ wv,
    const float* __restrict__ g1, const float* __restrict__ be1) {
    __shared__ __align__(16) float wsh[HDIM * DD];      // 32 KB, reused for wq/wk/wv
    int tid = threadIdx.x;
    int s = blockIdx.x * 256 + tid;
    int orig = (int)(g_sort[s] & 0xffffffffULL);

    float xv[32];
    const float4* xp = (const float4*)(x + orig * 32);
#pragma unroll
    for (int q8 = 0; q8 < 8; q8++) {
        float4 t = xp[q8];
        xv[4 * q8] = t.x; xv[4 * q8 + 1] = t.y; xv[4 * q8 + 2] = t.z; xv[4 * q8 + 3] = t.w;
    }
    float mu = 0.f;
#pragma unroll
    for (int d = 0; d < 32; d++) mu += xv[d];
    mu *= (1.f / 32.f);
    float var = 0.f;
#pragma unroll
    for (int d = 0; d < 32; d++) { float c = xv[d] - mu; var = fmaf(c, c, var); }
    var *= (1.f / 32.f);
    float inv = rsqrtf(var + 1e-5f);
#pragma unroll
    for (int d = 0; d < 32; d++) xv[d] = (xv[d] - mu) * inv * g1[d] + be1[d];

    // sorted spatial coords (dims 1,2)
    g_p[2 * s]     = coords[3 * orig + 1];
    g_p[2 * s + 1] = coords[3 * orig + 2];

    int b = blockIdx.x;   // one CTA == one attention block of 256 tokens
    float* qdst = g_q + b * 65536 + tid;
    float* kdst = g_k + b * 65536 + tid;
    float* vdst = g_v + b * 65536 + tid;
    do_proj(wq, qdst, xv, wsh, tid);
    do_proj(wk, kdst, xv, wsh, tid);
    do_proj(wv, vdst, xv, wsh, tid);
}

// ---------------- block attention: CTA = (block, head), thread = query row ----------------
__global__ void __launch_bounds__(256) attn_kernel() {
    __shared__ __align__(16) float ksh[BLK * DD];   // 32 KB
    __shared__ __align__(16) float psh[BLK * 2];    // 2 KB
    int tid = threadIdx.x;
    int bh = blockIdx.x;              // b*8+h
    int b = bh >> 3, h = bh & 7;

    const float* kg = g_k + bh * 8192;
    const float* vg = g_v + bh * 8192;
    const float4* kg4 = (const float4*)kg;
    float4* k4 = (float4*)ksh;
#pragma unroll
    for (int u = 0; u < 8; u++) k4[tid + 256 * u] = kg4[tid + 256 * u];
    if (tid < 128) ((float4*)psh)[tid] = ((const float4*)(g_p + b * 512))[tid];
    __syncthreads();

    int i = tid;
    float qv[32];
    const float* qgp = g_q + bh * 8192 + i;
    const float scale = 0.17677669529663687f;  // 1/sqrt(32)
#pragma unroll
    for (int d = 0; d < 32; d++) qv[d] = qgp[d * 256] * scale;   // coalesced per d
    float pi0 = psh[2 * i], pi1 = psh[2 * i + 1];
    float w20 = g_w2[2 * h], w21 = g_w2[2 * h + 1];

    float o[32];
#pragma unroll
    for (int d = 0; d < 32; d++) o[d] = 0.f;
    float lsum = 0.f;

    // scores are tiny (|s| < ~1) -> plain exp, no max-subtraction needed
    for (int j4 = 0; j4 < 256; j4 += 4) {
        float s0 = 0.f, s1 = 0.f, s2 = 0.f, s3 = 0.f;
#pragma unroll
        for (int d = 0; d < 32; d++) {
            float4 kk = *(const float4*)(ksh + d * 256 + j4);   // warp-broadcast LDS.128
            s0 = fmaf(qv[d], kk.x, s0);
            s1 = fmaf(qv[d], kk.y, s1);
            s2 = fmaf(qv[d], kk.z, s2);
            s3 = fmaf(qv[d], kk.w, s3);
        }
        float4 pj01 = *(const float4*)(psh + 2 * j4);
        float4 pj23 = *(const float4*)(psh + 2 * j4 + 4);
        float dx, dy;
        dx = pi0 - pj01.x; dy = pi1 - pj01.y; float bb0 = fmaf(w20, dx * dx, w21 * dy * dy);
        dx = pi0 - pj01.z; dy = pi1 - pj01.w; float bb1 = fmaf(w20, dx * dx, w21 * dy * dy);
        dx = pi0 - pj23.x; dy = pi1 - pj23.y; float bb2 = fmaf(w20, dx * dx, w21 * dy * dy);
        dx = pi0 - pj23.z; dy = pi1 - pj23.w; float bb3 = fmaf(w20, dx * dx, w21 * dy * dy);
        float e0 = __expf(s0 - bb0);
        float e1 = __expf(s1 - bb1);
        float e2 = __expf(s2 - bb2);
        float e3 = __expf(s3 - bb3);
        lsum += (e0 + e1) + (e2 + e3);
#pragma unroll
        for (int d = 0; d < 32; d++) {
            float4 vv = __ldg((const float4*)(vg + d * 256 + j4));  // broadcast via L1
            o[d] = fmaf(e0, vv.x, o[d]);
            o[d] = fmaf(e1, vv.y, o[d]);
            o[d] = fmaf(e2, vv.z, o[d]);
            o[d] = fmaf(e3, vv.w, o[d]);
        }
    }
    float linv = 1.f / lsum;
    float* og = g_att + bh * 8192 + i;
#pragma unroll
    for (int d = 0; d < 32; d++) og[d * 256] = o[d] * linv;   // coalesced per d
}

// ---------------- fused epilogue: out-proj + unsort + residual + LN2 + FFN + residual ----------------
__global__ void __launch_bounds__(256) epi_kernel(
    const float* __restrict__ x, const float* __restrict__ wout, const float* __restrict__ bout,
    const float* __restrict__ g2, const float* __restrict__ be2,
    const float* __restrict__ fw1, const float* __restrict__ fb1,
    const float* __restrict__ fw2, const float* __restrict__ fb2,
    float* __restrict__ out) {
    __shared__ __align__(16) float wsh[DD * HDIM];   // w_out, 32 KB
    __shared__ __align__(16) float w1sh[DD * DD];    // 4 KB
    __shared__ __align__(16) float w2sh[DD * DD];    // 4 KB
    int tid = threadIdx.x;
#pragma unroll
    for (int u = 0; u < 8; u++) ((float4*)wsh)[tid + 256 * u] = ((const float4*)wout)[tid + 256 * u];
    ((float4*)w1sh)[tid] = ((const float4*)fw1)[tid];
    ((float4*)w2sh)[tid] = ((const float4*)fw2)[tid];
    __syncthreads();

    int b = blockIdx.x, i = tid;
    int s = b * 256 + i;
    const float* ag = g_att + b * 65536 + i;

    float y[32];
#pragma unroll
    for (int d = 0; d < 32; d++) y[d] = 0.f;
#pragma unroll 4
    for (int hd = 0; hd < 256; hd++) {
        float v = ag[((hd >> 5) << 13) + ((hd & 31) << 8)];   // coalesced
#pragma unroll
        for (int d = 0; d < 32; d++) y[d] = fmaf(v, wsh[d * 256 + hd], y[d]);
    }

    int orig = (int)(g_sort[s] & 0xffffffffULL);
    float x2[32];
    const float4* xp = (const float4*)(x + orig * 32);
#pragma unroll
    for (int q8 = 0; q8 < 8; q8++) {
        float4 t = xp[q8];
        x2[4 * q8]     = t.x + y[4 * q8]     + bout[4 * q8];
        x2[4 * q8 + 1] = t.y + y[4 * q8 + 1] + bout[4 * q8 + 1];
        x2[4 * q8 + 2] = t.z + y[4 * q8 + 2] + bout[4 * q8 + 2];
        x2[4 * q8 + 3] = t.w + y[4 * q8 + 3] + bout[4 * q8 + 3];
    }

    // LayerNorm 2
    float mu = 0.f;
#pragma unroll
    for (int d = 0; d < 32; d++) mu += x2[d];
    mu *= (1.f / 32.f);
    float var = 0.f;
#pragma unroll
    for (int d = 0; d < 32; d++) { float c = x2[d] - mu; var = fmaf(c, c, var); }
    var *= (1.f / 32.f);
    float inv = rsqrtf(var + 1e-5f);
    float ln[32];
#pragma unroll
    for (int d = 0; d < 32; d++) ln[d] = (x2[d] - mu) * inv * g2[d] + be2[d];

    // FFN layer 1 (relu)
    float h1[32];
#pragma unroll
    for (int o = 0; o < 32; o++) {
        const float4* wr4 = (const float4*)(w1sh + o * 32);
        float acc = fb1[o];
#pragma unroll
        for (int q8 = 0; q8 < 8; q8++) {
            float4 w4 = wr4[q8];
            acc = fmaf(ln[4 * q8], w4.x, acc);
            acc = fmaf(ln[4 * q8 + 1], w4.y, acc);
            acc = fmaf(ln[4 * q8 + 2], w4.z, acc);
            acc = fmaf(ln[4 * q8 + 3], w4.w, acc);
        }
        h1[o] = fmaxf(acc, 0.f);
    }
    // FFN layer 2 + residual, scatter to original order
    float res[32];
#pragma unroll
    for (int o = 0; o < 32; o++) {
        const float4* wr4 = (const float4*)(w2sh + o * 32);
        float acc = fb2[o];
#pragma unroll
        for (int q8 = 0; q8 < 8; q8++) {
            float4 w4 = wr4[q8];
            acc = fmaf(h1[4 * q8], w4.x, acc);
            acc = fmaf(h1[4 * q8 + 1], w4.y, acc);
            acc = fmaf(h1[4 * q8 + 2], w4.z, acc);
            acc = fmaf(h1[4 * q8 + 3], w4.w, acc);
        }
        res[o] = x2[o] + acc;
    }
    float4* op = (float4*)(out + orig * 32);
#pragma unroll
    for (int q8 = 0; q8 < 8; q8++) {
        float4 t;
        t.x = res[4 * q8]; t.y = res[4 * q8 + 1]; t.z = res[4 * q8 + 2]; t.w = res[4 * q8 + 3];
        op[q8] = t;
    }
}

// ---------------- host launcher ----------------
extern "C" void kernel_launch(void* const* d_in, const int* in_sizes, int n_in,
                              void* d_out, int out_size) {
    const float* x      = (const float*)d_in[0];
    const float* coords = (const float*)d_in[1];
    const float* wq     = (const float*)d_in[2];
    const float* wk     = (const float*)d_in[3];
    const float* wv     = (const float*)d_in[4];
    const float* wrpe   = (const float*)d_in[5];
    const float* wout   = (const float*)d_in[6];
    const float* bout   = (const float*)d_in[7];
    const float* g1     = (const float*)d_in[8];
    const float* be1    = (const float*)d_in[9];
    const float* g2     = (const float*)d_in[10];
    const float* be2    = (const float*)d_in[11];
    const float* fw1    = (const float*)d_in[12];
    const float* fb1    = (const float*)d_in[13];
    const float* fw2    = (const float*)d_in[14];
    const float* fb2    = (const float*)d_in[15];
    float* out = (float*)d_out;

    // stable sort by coords[:,0] (index in low bits breaks ties)
    sort_init_local<<<32, 1024>>>(coords);
    for (int k = 4096; k <= 65536; k <<= 1) {
        for (int j = k >> 1; j >= 2048; j >>= 1) sort_gpass<<<128, 256>>>(k, j);
        sort_lfinish<<<32, 1024>>>(k);
    }
    calc_w2<<<1, 32>>>(wrpe);
    proj_kernel<<<NBLK, 256>>>(x, coords, wq, wk, wv, g1, be1);
    attn_kernel<<<NBLK * NH, 256>>>();
    epi_kernel<<<NBLK, 256>>>(x, wout, bout, g2, be2, fw1, fb1, fw2, fb2, out);
}

// round 3
// speedup vs baseline: 3.3673x; 3.3673x over previous
#include <cuda_runtime.h>
#include <cuda_bf16.h>
#include <math.h>
#include <stdint.h>

#define N_TOK 65536
#define DD 32
#define NH 8
#define HDIM 256
#define BLK 256
#define NBLK 256

// ---------------- device scratch ----------------
__device__ unsigned long long g_sort[N_TOK];                  // (key<<32)|idx
__device__ __align__(16) unsigned g_qbw[N_TOK * HDIM / 2];    // bf16x2 [bh][i][d/2], q pre-scaled
__device__ __align__(16) unsigned g_kbw[N_TOK * HDIM / 2];    // bf16x2 [bh][i][d/2]
__device__ __align__(16) __nv_bfloat16 g_vb[N_TOK * HDIM];    // [bh][d][i]
__device__ float g_att[N_TOK * HDIM];                         // [bh][d][i] fp32
__device__ float g_p[N_TOK * 2];                              // sorted coords dims 1,2
__device__ float g_w2[NH * 2];

// ---------------- helpers ----------------
__device__ __forceinline__ unsigned pack_bf16x2(float lo, float hi) {
    unsigned r;
    asm("cvt.rn.bf16x2.f32 %0, %1, %2;" : "=r"(r) : "f"(hi), "f"(lo));
    return r;
}
__device__ __forceinline__ void mma_bf16(float c[4], const unsigned a[4],
                                         unsigned b0, unsigned b1) {
    asm volatile("mma.sync.aligned.m16n8k16.row.col.f32.bf16.bf16.f32 "
                 "{%0,%1,%2,%3}, {%4,%5,%6,%7}, {%8,%9}, {%0,%1,%2,%3};"
                 : "+f"(c[0]), "+f"(c[1]), "+f"(c[2]), "+f"(c[3])
                 : "r"(a[0]), "r"(a[1]), "r"(a[2]), "r"(a[3]), "r"(b0), "r"(b1));
}

// ---------------- bitonic sort (stable via idx in low bits) ----------------
__global__ void sort_init_local(const float* __restrict__ coords) {
    __shared__ unsigned long long sh[2048];
    int tid = threadIdx.x;
    int base = blockIdx.x * 2048;
    for (int t = tid; t < 2048; t += 1024) {
        int gi = base + t;
        unsigned key = __float_as_uint(coords[3 * gi]);
        sh[t] = ((unsigned long long)key << 32) | (unsigned)gi;
    }
    __syncthreads();
    for (int k = 2; k <= 2048; k <<= 1) {
        for (int j = k >> 1; j > 0; j >>= 1) {
            for (int t = tid; t < 2048; t += 1024) {
                int p = t ^ j;
                if (p > t) {
                    bool up = (((base + t) & k) == 0);
                    unsigned long long a = sh[t], b = sh[p];
                    if ((a > b) == up) { sh[t] = b; sh[p] = a; }
                }
            }
            __syncthreads();
        }
    }
    for (int t = tid; t < 2048; t += 1024) g_sort[base + t] = sh[t];
}

__global__ void sort_gpass(int k, int j) {
    int t = blockIdx.x * blockDim.x + threadIdx.x;
    int l = ((t & ~(j - 1)) << 1) | (t & (j - 1));
    int p = l | j;
    bool up = ((l & k) == 0);
    unsigned long long a = g_sort[l], b = g_sort[p];
    if ((a > b) == up) { g_sort[l] = b; g_sort[p] = a; }
}

__global__ void sort_lfinish(int k) {
    __shared__ unsigned long long sh[2048];
    int tid = threadIdx.x;
    int base = blockIdx.x * 2048;
    for (int t = tid; t < 2048; t += 1024) sh[t] = g_sort[base + t];
    __syncthreads();
    bool up = ((base & k) == 0);
    for (int j = 1024; j > 0; j >>= 1) {
        for (int t = tid; t < 2048; t += 1024) {
            int p = t ^ j;
            if (p > t) {
                unsigned long long a = sh[t], b = sh[p];
                if ((a > b) == up) { sh[t] = b; sh[p] = a; }
            }
        }
        __syncthreads();
    }
    for (int t = tid; t < 2048; t += 1024) g_sort[base + t] = sh[t];
}

// ---------------- RPE weights ----------------
__global__ void calc_w2(const float* __restrict__ wrpe) {
    int t = threadIdx.x;
    if (t < 16) {
        int h = t >> 1, c = t & 1;
        float acc = 0.f;
        for (int d = 0; d < 32; d++)
            for (int w = 0; w < 8; w++) {
                float v = wrpe[(h * 32 + d) * 16 + c * 8 + w];
                acc += v * v;
            }
        g_w2[t] = acc * (1.f / 256.f);
    }
}

// ---------------- LayerNorm + QKV projection (bf16 outputs) ----------------
__global__ void __launch_bounds__(256) proj_kernel(
    const float* __restrict__ x, const float* __restrict__ coords,
    const float* __restrict__ wq, const float* __restrict__ wk, const float* __restrict__ wv,
    const float* __restrict__ g1, const float* __restrict__ be1) {
    __shared__ __align__(16) float wsh[HDIM * DD];   // 32 KB
    int tid = threadIdx.x;
    int b = blockIdx.x;
    int s = b * 256 + tid;
    int orig = (int)(g_sort[s] & 0xffffffffULL);

    float xv[32];
    const float4* xp = (const float4*)(x + orig * 32);
#pragma unroll
    for (int q8 = 0; q8 < 8; q8++) {
        float4 t = xp[q8];
        xv[4 * q8] = t.x; xv[4 * q8 + 1] = t.y; xv[4 * q8 + 2] = t.z; xv[4 * q8 + 3] = t.w;
    }
    float mu = 0.f;
#pragma unroll
    for (int d = 0; d < 32; d++) mu += xv[d];
    mu *= (1.f / 32.f);
    float var = 0.f;
#pragma unroll
    for (int d = 0; d < 32; d++) { float c = xv[d] - mu; var = fmaf(c, c, var); }
    var *= (1.f / 32.f);
    float inv = rsqrtf(var + 1e-5f);
#pragma unroll
    for (int d = 0; d < 32; d++) xv[d] = (xv[d] - mu) * inv * g1[d] + be1[d];

    g_p[2 * s]     = coords[3 * orig + 1];
    g_p[2 * s + 1] = coords[3 * orig + 2];

    // ---- Q (scaled) ----
    {
        __syncthreads();
#pragma unroll
        for (int u = 0; u < 8; u++) ((float4*)wsh)[tid + 256 * u] = ((const float4*)wq)[tid + 256 * u];
        __syncthreads();
        const float scale = 0.17677669529663687f;   // 1/sqrt(32)
#pragma unroll 2
        for (int o4 = 0; o4 < 64; o4++) {
            float a[4];
#pragma unroll
            for (int ss = 0; ss < 4; ss++) {
                const float4* wr4 = (const float4*)(wsh + (o4 * 4 + ss) * 32);
                float acc = 0.f;
#pragma unroll
                for (int q8 = 0; q8 < 8; q8++) {
                    float4 w4 = wr4[q8];
                    acc = fmaf(xv[4 * q8 + 0], w4.x, acc);
                    acc = fmaf(xv[4 * q8 + 1], w4.y, acc);
                    acc = fmaf(xv[4 * q8 + 2], w4.z, acc);
                    acc = fmaf(xv[4 * q8 + 3], w4.w, acc);
                }
                a[ss] = acc * scale;
            }
            int o = o4 * 4, h = o >> 5, dw = (o & 31) >> 1;
            unsigned* dst = g_qbw + ((size_t)((b * 8 + h) * 256 + tid)) * 16 + dw;
            dst[0] = pack_bf16x2(a[0], a[1]);
            dst[1] = pack_bf16x2(a[2], a[3]);
        }
    }
    // ---- K ----
    {
        __syncthreads();
#pragma unroll
        for (int u = 0; u < 8; u++) ((float4*)wsh)[tid + 256 * u] = ((const float4*)wk)[tid + 256 * u];
        __syncthreads();
#pragma unroll 2
        for (int o4 = 0; o4 < 64; o4++) {
            float a[4];
#pragma unroll
            for (int ss = 0; ss < 4; ss++) {
                const float4* wr4 = (const float4*)(wsh + (o4 * 4 + ss) * 32);
                float acc = 0.f;
#pragma unroll
                for (int q8 = 0; q8 < 8; q8++) {
                    float4 w4 = wr4[q8];
                    acc = fmaf(xv[4 * q8 + 0], w4.x, acc);
                    acc = fmaf(xv[4 * q8 + 1], w4.y, acc);
                    acc = fmaf(xv[4 * q8 + 2], w4.z, acc);
                    acc = fmaf(xv[4 * q8 + 3], w4.w, acc);
                }
                a[ss] = acc;
            }
            int o = o4 * 4, h = o >> 5, dw = (o & 31) >> 1;
            unsigned* dst = g_kbw + ((size_t)((b * 8 + h) * 256 + tid)) * 16 + dw;
            dst[0] = pack_bf16x2(a[0], a[1]);
            dst[1] = pack_bf16x2(a[2], a[3]);
        }
    }
    // ---- V (d-major bf16, coalesced 2B stores) ----
    {
        __syncthreads();
#pragma unroll
        for (int u = 0; u < 8; u++) ((float4*)wsh)[tid + 256 * u] = ((const float4*)wv)[tid + 256 * u];
        __syncthreads();
#pragma unroll 4
        for (int o = 0; o < 256; o++) {
            const float4* wr4 = (const float4*)(wsh + o * 32);
            float acc = 0.f;
#pragma unroll
            for (int q8 = 0; q8 < 8; q8++) {
                float4 w4 = wr4[q8];
                acc = fmaf(xv[4 * q8 + 0], w4.x, acc);
                acc = fmaf(xv[4 * q8 + 1], w4.y, acc);
                acc = fmaf(xv[4 * q8 + 2], w4.z, acc);
                acc = fmaf(xv[4 * q8 + 3], w4.w, acc);
            }
            int h = o >> 5, d = o & 31;
            g_vb[((size_t)(b * 8 + h) * 32 + d) * 256 + tid] = __float2bfloat16(acc);
        }
    }
}

// ---------------- HMMA block attention ----------------
// CTA = (block b, head h). 8 warps; warp w handles query rows w*32..w*32+31.
// score = q.k/sqrt(D) + 2w0 xi xj + 2w1 yi yj - cj  (row term ri cancels in softmax)
__global__ void __launch_bounds__(256) attn_hmma_kernel() {
    __shared__ __align__(16) unsigned Ksh[256 * 16];   // 16 KB, [j][w^swz(j)]
    __shared__ __align__(16) unsigned Vsh[32 * 128];   // 16 KB, [d][wj^swz(d)]
    __shared__ __align__(16) float2 psh2[256];         // 2 KB
    __shared__ float cj[256];                          // 1 KB

    int tid = threadIdx.x, wid = tid >> 5, lane = tid & 31;
    int bh = blockIdx.x;
    int b = bh >> 3, h = bh & 7;
    float w20 = g_w2[2 * h], w21 = g_w2[2 * h + 1];

    // load K tile: thread t = row j, 16 words, swizzled store
    {
        int j = tid;
        const uint4* src = (const uint4*)(g_kbw + ((size_t)(bh * 256 + j)) * 16);
        int xr = ((j >> 1) & 3) << 2;
#pragma unroll
        for (int wg = 0; wg < 4; wg++) {
            uint4 v = src[wg];
            Ksh[j * 16 + ((wg * 4 + 0) ^ xr)] = v.x;
            Ksh[j * 16 + ((wg * 4 + 1) ^ xr)] = v.y;
            Ksh[j * 16 + ((wg * 4 + 2) ^ xr)] = v.z;
            Ksh[j * 16 + ((wg * 4 + 3) ^ xr)] = v.w;
        }
    }
    // load V tile: thread t -> d = t/8, 16 words
    {
        int d = tid >> 3, w0 = (tid & 7) * 16;
        const uint4* src = (const uint4*)((const unsigned*)g_vb + ((size_t)(bh * 32 + d)) * 128 + w0);
        int xr = (d & 7) << 2;
#pragma unroll
        for (int wg = 0; wg < 4; wg++) {
            uint4 v = src[wg];
            Vsh[d * 128 + ((w0 + wg * 4 + 0) ^ xr)] = v.x;
            Vsh[d * 128 + ((w0 + wg * 4 + 1) ^ xr)] = v.y;
            Vsh[d * 128 + ((w0 + wg * 4 + 2) ^ xr)] = v.z;
            Vsh[d * 128 + ((w0 + wg * 4 + 3) ^ xr)] = v.w;
        }
    }
    // coords + per-column bias constant
    {
        float2 p = ((const float2*)(g_p + b * 512))[tid];
        psh2[tid] = p;
        cj[tid] = w20 * p.x * p.x + w21 * p.y * p.y;
    }
    __syncthreads();

    // ---- per-warp Q fragments (k=32 -> 2 k-steps), loaded from global ----
    int mi = wid * 32;
    int i0 = mi + (lane >> 2);
    const unsigned* qw = g_qbw + ((size_t)bh * 256) * 16;
    unsigned qf[2][2][4];
#pragma unroll
    for (int m = 0; m < 2; m++)
#pragma unroll
        for (int s = 0; s < 2; s++) {
            int ib = i0 + m * 16;
            int kw = s * 8 + (lane & 3);
            qf[m][s][0] = qw[ib * 16 + kw];
            qf[m][s][1] = qw[(ib + 8) * 16 + kw];
            qf[m][s][2] = qw[ib * 16 + kw + 4];
            qf[m][s][3] = qw[(ib + 8) * 16 + kw + 4];
        }
    // extras A fragment: rows carry (2*w0*xi, 2*w1*yi) in k-cols 0,1 only
    unsigned ax[2][4];
#pragma unroll
    for (int m = 0; m < 2; m++) {
        float2 pa = psh2[i0 + m * 16];
        float2 pb = psh2[i0 + m * 16 + 8];
        ax[m][0] = ((lane & 3) == 0) ? pack_bf16x2(2.f * w20 * pa.x, 2.f * w21 * pa.y) : 0u;
        ax[m][1] = ((lane & 3) == 0) ? pack_bf16x2(2.f * w20 * pb.x, 2.f * w21 * pb.y) : 0u;
        ax[m][2] = 0u; ax[m][3] = 0u;
    }

    float oacc[2][4][4];
#pragma unroll
    for (int m = 0; m < 2; m++)
#pragma unroll
        for (int n = 0; n < 4; n++)
#pragma unroll
            for (int e = 0; e < 4; e++) oacc[m][n][e] = 0.f;
    float lsum[4] = {0.f, 0.f, 0.f, 0.f};

    for (int c = 0; c < 16; c++) {
        int n0 = c * 16;
        // K B-fragments for 2 k-steps x 2 n-frags
        unsigned kb[2][2][2], xb[2][2];
#pragma unroll
        for (int f = 0; f < 2; f++) {
            int j = n0 + f * 8 + (lane >> 2);
            int xr = ((j >> 1) & 3) << 2;
#pragma unroll
            for (int s = 0; s < 2; s++) {
                int w0 = s * 8 + (lane & 3);
                kb[s][f][0] = Ksh[j * 16 + (w0 ^ xr)];
                kb[s][f][1] = Ksh[j * 16 + ((w0 + 4) ^ xr)];
            }
            float2 pj = psh2[j];
            xb[f][0] = ((lane & 3) == 0) ? pack_bf16x2(pj.x, pj.y) : 0u;
            xb[f][1] = 0u;
        }
        // S = Q K^T + cross terms
        float sa[2][2][4];
#pragma unroll
        for (int m = 0; m < 2; m++)
#pragma unroll
            for (int f = 0; f < 2; f++) {
#pragma unroll
                for (int e = 0; e < 4; e++) sa[m][f][e] = 0.f;
                mma_bf16(sa[m][f], qf[m][0], kb[0][f][0], kb[0][f][1]);
                mma_bf16(sa[m][f], qf[m][1], kb[1][f][0], kb[1][f][1]);
                mma_bf16(sa[m][f], ax[m], xb[f][0], xb[f][1]);
            }
        // exp epilogue + repack to A fragments (FA2 layout identity)
        unsigned pA[2][4];
#pragma unroll
        for (int m = 0; m < 2; m++)
#pragma unroll
            for (int f = 0; f < 2; f++) {
                int jj = n0 + f * 8 + (lane & 3) * 2;
                float cj0 = cj[jj], cj1 = cj[jj + 1];
                float e0 = __expf(sa[m][f][0] - cj0);
                float e1 = __expf(sa[m][f][1] - cj1);
                float e2 = __expf(sa[m][f][2] - cj0);
                float e3 = __expf(sa[m][f][3] - cj1);
                lsum[m * 2 + 0] += e0 + e1;
                lsum[m * 2 + 1] += e2 + e3;
                pA[m][f * 2 + 0] = pack_bf16x2(e0, e1);
                pA[m][f * 2 + 1] = pack_bf16x2(e2, e3);
            }
        // O += P V
#pragma unroll
        for (int n2 = 0; n2 < 4; n2++) {
            int d = n2 * 8 + (lane >> 2);
            int xr = (d & 7) << 2;
            int wj = n0 / 2 + (lane & 3);
            unsigned vb0 = Vsh[d * 128 + (wj ^ xr)];
            unsigned vb1 = Vsh[d * 128 + ((wj + 4) ^ xr)];
            mma_bf16(oacc[0][n2], pA[0], vb0, vb1);
            mma_bf16(oacc[1][n2], pA[1], vb0, vb1);
        }
    }

    // row-sum reduction across the quad (lanes sharing rows)
#pragma unroll
    for (int r = 0; r < 4; r++) {
        lsum[r] += __shfl_xor_sync(0xffffffffu, lsum[r], 1);
        lsum[r] += __shfl_xor_sync(0xffffffffu, lsum[r], 2);
    }
    float linv[4];
#pragma unroll
    for (int r = 0; r < 4; r++) linv[r] = 1.f / lsum[r];

    float* og = g_att + (size_t)bh * 8192;
#pragma unroll
    for (int m = 0; m < 2; m++) {
        int ia = mi + m * 16 + (lane >> 2);
#pragma unroll
        for (int n2 = 0; n2 < 4; n2++) {
            int d0 = n2 * 8 + (lane & 3) * 2;
            og[d0 * 256 + ia]             = oacc[m][n2][0] * linv[m * 2];
            og[(d0 + 1) * 256 + ia]       = oacc[m][n2][1] * linv[m * 2];
            og[d0 * 256 + ia + 8]         = oacc[m][n2][2] * linv[m * 2 + 1];
            og[(d0 + 1) * 256 + ia + 8]   = oacc[m][n2][3] * linv[m * 2 + 1];
        }
    }
}

// ---------------- fused epilogue ----------------
__global__ void __launch_bounds__(256) epi_kernel(
    const float* __restrict__ x, const float* __restrict__ wout, const float* __restrict__ bout,
    const float* __restrict__ g2, const float* __restrict__ be2,
    const float* __restrict__ fw1, const float* __restrict__ fb1,
    const float* __restrict__ fw2, const float* __restrict__ fb2,
    float* __restrict__ out) {
    __shared__ __align__(16) float wsh[DD * HDIM];
    __shared__ __align__(16) float w1sh[DD * DD];
    __shared__ __align__(16) float w2sh[DD * DD];
    int tid = threadIdx.x;
#pragma unroll
    for (int u = 0; u < 8; u++) ((float4*)wsh)[tid + 256 * u] = ((const float4*)wout)[tid + 256 * u];
    ((float4*)w1sh)[tid] = ((const float4*)fw1)[tid];
    ((float4*)w2sh)[tid] = ((const float4*)fw2)[tid];
    __syncthreads();

    int b = blockIdx.x, i = tid;
    int s = b * 256 + i;
    const float* ag = g_att + (size_t)b * 65536 + i;

    float y[32];
#pragma unroll
    for (int d = 0; d < 32; d++) y[d] = 0.f;
#pragma unroll 4
    for (int hd = 0; hd < 256; hd++) {
        float v = ag[((hd >> 5) << 13) + ((hd & 31) << 8)];
#pragma unroll
        for (int d = 0; d < 32; d++) y[d] = fmaf(v, wsh[d * 256 + hd], y[d]);
    }

    int orig = (int)(g_sort[s] & 0xffffffffULL);
    float x2[32];
    const float4* xp = (const float4*)(x + orig * 32);
#pragma unroll
    for (int q8 = 0; q8 < 8; q8++) {
        float4 t = xp[q8];
        x2[4 * q8]     = t.x + y[4 * q8]     + bout[4 * q8];
        x2[4 * q8 + 1] = t.y + y[4 * q8 + 1] + bout[4 * q8 + 1];
        x2[4 * q8 + 2] = t.z + y[4 * q8 + 2] + bout[4 * q8 + 2];
        x2[4 * q8 + 3] = t.w + y[4 * q8 + 3] + bout[4 * q8 + 3];
    }

    float mu = 0.f;
#pragma unroll
    for (int d = 0; d < 32; d++) mu += x2[d];
    mu *= (1.f / 32.f);
    float var = 0.f;
#pragma unroll
    for (int d = 0; d < 32; d++) { float c = x2[d] - mu; var = fmaf(c, c, var); }
    var *= (1.f / 32.f);
    float inv = rsqrtf(var + 1e-5f);
    float ln[32];
#pragma unroll
    for (int d = 0; d < 32; d++) ln[d] = (x2[d] - mu) * inv * g2[d] + be2[d];

    float h1[32];
#pragma unroll
    for (int o = 0; o < 32; o++) {
        const float4* wr4 = (const float4*)(w1sh + o * 32);
        float acc = fb1[o];
#pragma unroll
        for (int q8 = 0; q8 < 8; q8++) {
            float4 w4 = wr4[q8];
            acc = fmaf(ln[4 * q8], w4.x, acc);
            acc = fmaf(ln[4 * q8 + 1], w4.y, acc);
            acc = fmaf(ln[4 * q8 + 2], w4.z, acc);
            acc = fmaf(ln[4 * q8 + 3], w4.w, acc);
        }
        h1[o] = fmaxf(acc, 0.f);
    }
    float res[32];
#pragma unroll
    for (int o = 0; o < 32; o++) {
        const float4* wr4 = (const float4*)(w2sh + o * 32);
        float acc = fb2[o];
#pragma unroll
        for (int q8 = 0; q8 < 8; q8++) {
            float4 w4 = wr4[q8];
            acc = fmaf(h1[4 * q8], w4.x, acc);
            acc = fmaf(h1[4 * q8 + 1], w4.y, acc);
            acc = fmaf(h1[4 * q8 + 2], w4.z, acc);
            acc = fmaf(h1[4 * q8 + 3], w4.w, acc);
        }
        res[o] = x2[o] + acc;
    }
    float4* op = (float4*)(out + orig * 32);
#pragma unroll
    for (int q8 = 0; q8 < 8; q8++)
        op[q8] = make_float4(res[4 * q8], res[4 * q8 + 1], res[4 * q8 + 2], res[4 * q8 + 3]);
}

// ---------------- host launcher ----------------
extern "C" void kernel_launch(void* const* d_in, const int* in_sizes, int n_in,
                              void* d_out, int out_size) {
    const float* x      = (const float*)d_in[0];
    const float* coords = (const float*)d_in[1];
    const float* wq     = (const float*)d_in[2];
    const float* wk     = (const float*)d_in[3];
    const float* wv     = (const float*)d_in[4];
    const float* wrpe   = (const float*)d_in[5];
    const float* wout   = (const float*)d_in[6];
    const float* bout   = (const float*)d_in[7];
    const float* g1     = (const float*)d_in[8];
    const float* be1    = (const float*)d_in[9];
    const float* g2     = (const float*)d_in[10];
    const float* be2    = (const float*)d_in[11];
    const float* fw1    = (const float*)d_in[12];
    const float* fb1    = (const float*)d_in[13];
    const float* fw2    = (const float*)d_in[14];
    const float* fb2    = (const float*)d_in[15];
    float* out = (float*)d_out;

    sort_init_local<<<32, 1024>>>(coords);
    for (int k = 4096; k <= 65536; k <<= 1) {
        for (int j = k >> 1; j >= 2048; j >>= 1) sort_gpass<<<128, 256>>>(k, j);
        sort_lfinish<<<32, 1024>>>(k);
    }
    calc_w2<<<1, 32>>>(wrpe);
    proj_kernel<<<NBLK, 256>>>(x, coords, wq, wk, wv, g1, be1);
    attn_hmma_kernel<<<NBLK * NH, 256>>>();
    epi_kernel<<<NBLK, 256>>>(x, wout, bout, g2, be2, fw1, fb1, fw2, fb2, out);
}

// round 4
// speedup vs baseline: 6.0483x; 1.7962x over previous
#include <cuda_runtime.h>
#include <cuda_bf16.h>
#include <math.h>
#include <stdint.h>

#define N_TOK 65536
#define DD 32
#define NH 8
#define HDIM 256
#define BLK 256
#define NBLK 256

// ---------------- device scratch ----------------
__device__ unsigned long long g_sort[N_TOK];               // (key<<32)|idx
__device__ __align__(16) unsigned g_qbw[N_TOK * 128];      // bf16x2 [bh][i][16], q pre-scaled
__device__ __align__(16) unsigned g_kbw[N_TOK * 128];      // bf16x2 [bh][i][16]
__device__ __align__(16) unsigned g_vbw[N_TOK * 128];      // bf16x2 [bh][i][16] (token-major!)
__device__ __align__(16) unsigned g_attb[N_TOK * 128];     // bf16x2 [b][i][128] token-major
__device__ float g_p[N_TOK * 2];
__device__ float g_w2[16];
__device__ __align__(16) unsigned g_wqkvb[3 * 256 * 16];   // bf16x2 weights [w][o][16]
__device__ __align__(16) unsigned g_woutb[32 * 128];       // bf16x2 [o][128]

// ---------------- helpers ----------------
__device__ __forceinline__ unsigned pack_bf16x2(float lo, float hi) {
    unsigned r;
    asm("cvt.rn.bf16x2.f32 %0, %1, %2;" : "=r"(r) : "f"(hi), "f"(lo));
    return r;
}
__device__ __forceinline__ unsigned smem_u32(const void* p) {
    unsigned a;
    asm("{ .reg .u64 t; cvta.to.shared.u64 t, %1; cvt.u32.u64 %0, t; }" : "=r"(a) : "l"(p));
    return a;
}
__device__ __forceinline__ void mma_bf16(float c[4], const unsigned a[4],
                                         unsigned b0, unsigned b1) {
    asm volatile("mma.sync.aligned.m16n8k16.row.col.f32.bf16.bf16.f32 "
                 "{%0,%1,%2,%3}, {%4,%5,%6,%7}, {%8,%9}, {%0,%1,%2,%3};"
                 : "+f"(c[0]), "+f"(c[1]), "+f"(c[2]), "+f"(c[3])
                 : "r"(a[0]), "r"(a[1]), "r"(a[2]), "r"(a[3]), "r"(b0), "r"(b1));
}
__device__ __forceinline__ void ldm_x4(unsigned r[4], unsigned addr) {
    asm volatile("ldmatrix.sync.aligned.m8n8.x4.shared.b16 {%0,%1,%2,%3}, [%4];"
                 : "=r"(r[0]), "=r"(r[1]), "=r"(r[2]), "=r"(r[3]) : "r"(addr));
}
__device__ __forceinline__ void ldm_x4t(unsigned r[4], unsigned addr) {
    asm volatile("ldmatrix.sync.aligned.m8n8.x4.trans.shared.b16 {%0,%1,%2,%3}, [%4];"
                 : "=r"(r[0]), "=r"(r[1]), "=r"(r[2]), "=r"(r[3]) : "r"(addr));
}

// ---------------- bitonic sort ----------------
__global__ void sort_init_local(const float* __restrict__ coords) {
    __shared__ unsigned long long sh[2048];
    int tid = threadIdx.x;
    int base = blockIdx.x * 2048;
    for (int t = tid; t < 2048; t += 1024) {
        int gi = base + t;
        unsigned key = __float_as_uint(coords[3 * gi]);
        sh[t] = ((unsigned long long)key << 32) | (unsigned)gi;
    }
    __syncthreads();
    for (int k = 2; k <= 2048; k <<= 1) {
        for (int j = k >> 1; j > 0; j >>= 1) {
            for (int t = tid; t < 2048; t += 1024) {
                int p = t ^ j;
                if (p > t) {
                    bool up = (((base + t) & k) == 0);
                    unsigned long long a = sh[t], b = sh[p];
                    if ((a > b) == up) { sh[t] = b; sh[p] = a; }
                }
            }
            __syncthreads();
        }
    }
    for (int t = tid; t < 2048; t += 1024) g_sort[base + t] = sh[t];
}

// fused multistep global pass: thread owns 2^L elements at strides jL..jL<<(L-1), jL = 1<<P
template <int L, int P>
__global__ void sort_gmulti(int k) {
    constexpr int E = 1 << L;
    int t = blockIdx.x * blockDim.x + threadIdx.x;
    int base = ((t >> P) << (P + L)) | (t & ((1 << P) - 1));
    unsigned long long e[E];
#pragma unroll
    for (int m = 0; m < E; m++) e[m] = g_sort[base + (m << P)];
    bool up = ((base & k) == 0);
#pragma unroll
    for (int s = L - 1; s >= 0; s--) {
#pragma unroll
        for (int m = 0; m < E; m++) {
            if (!(m & (1 << s))) {
                int q = m | (1 << s);
                unsigned long long a = e[m], b = e[q];
                if ((a > b) == up) { e[m] = b; e[q] = a; }
            }
        }
    }
#pragma unroll
    for (int m = 0; m < E; m++) g_sort[base + (m << P)] = e[m];
}

__global__ void sort_lfinish(int k) {
    __shared__ unsigned long long sh[2048];
    int tid = threadIdx.x;
    int base = blockIdx.x * 2048;
    for (int t = tid; t < 2048; t += 1024) sh[t] = g_sort[base + t];
    __syncthreads();
    bool up = ((base & k) == 0);
    for (int j = 1024; j > 0; j >>= 1) {
        for (int t = tid; t < 2048; t += 1024) {
            int p = t ^ j;
            if (p > t) {
                unsigned long long a = sh[t], b = sh[p];
                if ((a > b) == up) { sh[t] = b; sh[p] = a; }
            }
        }
        __syncthreads();
    }
    for (int t = tid; t < 2048; t += 1024) g_sort[base + t] = sh[t];
}

// ---------------- prep: bf16 weight conversion + RPE w2 ----------------
__global__ void prep_kernel(const float* __restrict__ wq, const float* __restrict__ wk,
                            const float* __restrict__ wv, const float* __restrict__ wout,
                            const float* __restrict__ wrpe) {
    int gid = blockIdx.x * blockDim.x + threadIdx.x;   // 16384 threads
    if (gid < 12288) {
        const float* src = (gid < 4096) ? wq : (gid < 8192) ? wk : wv;
        int r = gid & 4095;
        int o = r >> 4, c = r & 15;
        g_wqkvb[gid] = pack_bf16x2(src[o * 32 + 2 * c], src[o * 32 + 2 * c + 1]);
    } else {
        int r = gid - 12288;
        int o = r >> 7, c = r & 127;
        g_woutb[r] = pack_bf16x2(wout[o * 256 + 2 * c], wout[o * 256 + 2 * c + 1]);
    }
    if (blockIdx.x == 0 && threadIdx.x < 16) {
        int h = threadIdx.x >> 1, c = threadIdx.x & 1;
        float acc = 0.f;
        for (int d = 0; d < 32; d++)
            for (int w = 0; w < 8; w++) {
                float v = wrpe[(h * 32 + d) * 16 + c * 8 + w];
                acc += v * v;
            }
        g_w2[threadIdx.x] = acc * (1.f / 256.f);
    }
}

// ---------------- LayerNorm + QKV projection via HMMA ----------------
__global__ void __launch_bounds__(256) proj_kernel(
    const float* __restrict__ x, const float* __restrict__ coords,
    const float* __restrict__ g1, const float* __restrict__ be1) {
    __shared__ __align__(16) unsigned xnsh[256 * 20];   // xn bf16x2, pitch 20 u32
    __shared__ __align__(16) unsigned wsh[256 * 20];    // weights bf16x2, pitch 20 u32
    int tid = threadIdx.x, wid = tid >> 5, lane = tid & 31;
    int b = blockIdx.x;
    int s = b * 256 + tid;
    int orig = (int)(g_sort[s] & 0xffffffffULL);

    float xv[32];
    const float4* xp = (const float4*)(x + orig * 32);
#pragma unroll
    for (int q8 = 0; q8 < 8; q8++) {
        float4 t = xp[q8];
        xv[4 * q8] = t.x; xv[4 * q8 + 1] = t.y; xv[4 * q8 + 2] = t.z; xv[4 * q8 + 3] = t.w;
    }
    float mu = 0.f;
#pragma unroll
    for (int d = 0; d < 32; d++) mu += xv[d];
    mu *= (1.f / 32.f);
    float var = 0.f;
#pragma unroll
    for (int d = 0; d < 32; d++) { float c = xv[d] - mu; var = fmaf(c, c, var); }
    var *= (1.f / 32.f);
    float inv = rsqrtf(var + 1e-5f);
#pragma unroll
    for (int d = 0; d < 32; d++) xv[d] = (xv[d] - mu) * inv * g1[d] + be1[d];

    g_p[2 * s]     = coords[3 * orig + 1];
    g_p[2 * s + 1] = coords[3 * orig + 2];

#pragma unroll
    for (int c = 0; c < 16; c++) xnsh[tid * 20 + c] = pack_bf16x2(xv[2 * c], xv[2 * c + 1]);
    __syncthreads();

    // A fragments (this warp's 32 rows), loaded once
    int r4 = lane >> 2, tig = lane & 3;
    int row0 = wid * 32 + r4;
    unsigned af[2][2][4];
#pragma unroll
    for (int m = 0; m < 2; m++)
#pragma unroll
        for (int ks = 0; ks < 2; ks++) {
            int rw = row0 + m * 16;
            af[m][ks][0] = xnsh[rw * 20 + ks * 8 + tig];
            af[m][ks][1] = xnsh[(rw + 8) * 20 + ks * 8 + tig];
            af[m][ks][2] = xnsh[rw * 20 + ks * 8 + tig + 4];
            af[m][ks][3] = xnsh[(rw + 8) * 20 + ks * 8 + tig + 4];
        }

    unsigned wbase = smem_u32(wsh);
    int lrow = lane & 7, lmat = lane >> 3;

    for (int w = 0; w < 3; w++) {
        if (w) __syncthreads();
        // load bf16 weights into smem (pitch 20)
#pragma unroll
        for (int c = 0; c < 16; c++) wsh[tid * 20 + c] = g_wqkvb[w * 4096 + tid * 16 + c];
        __syncthreads();

        unsigned* dst = (w == 0) ? g_qbw : (w == 1) ? g_kbw : g_vbw;
        float sc = (w == 0) ? 0.17677669529663687f : 1.f;

        for (int n0 = 0; n0 < 256; n0 += 8) {
            unsigned br[4];
            ldm_x4(br, wbase + (((n0 + lrow) * 20 + lmat * 4) << 2));
#pragma unroll
            for (int m = 0; m < 2; m++) {
                float acc[4] = {0.f, 0.f, 0.f, 0.f};
                mma_bf16(acc, af[m][0], br[0], br[1]);
                mma_bf16(acc, af[m][1], br[2], br[3]);
                int rw = row0 + m * 16;
                int h = n0 >> 5;
                size_t base = ((size_t)((b * 8 + h) * 256 + rw)) * 16 + ((n0 & 31) >> 1) + tig;
                dst[base]       = pack_bf16x2(acc[0] * sc, acc[1] * sc);
                dst[base + 128] = pack_bf16x2(acc[2] * sc, acc[3] * sc);
            }
        }
    }
}

// ---------------- HMMA block attention ----------------
__global__ void __launch_bounds__(256) attn_hmma_kernel() {
    __shared__ __align__(16) unsigned Ksh[256 * 20];    // [j][d], pitch 20 u32
    __shared__ __align__(16) unsigned Vsh[256 * 20];    // [j][d], pitch 20 u32
    __shared__ __align__(16) float2 psh2[256];
    __shared__ float cjs[256];

    int tid = threadIdx.x, wid = tid >> 5, lane = tid & 31;
    int bh = blockIdx.x;
    int b = bh >> 3, h = bh & 7;
    float w20 = g_w2[2 * h], w21 = g_w2[2 * h + 1];

    {
        const uint4* ks = (const uint4*)(g_kbw + ((size_t)bh * 256 + tid) * 16);
        unsigned* kd = Ksh + tid * 20;
#pragma unroll
        for (int u = 0; u < 4; u++) {
            uint4 t = ks[u];
            kd[4 * u] = t.x; kd[4 * u + 1] = t.y; kd[4 * u + 2] = t.z; kd[4 * u + 3] = t.w;
        }
        const uint4* vs = (const uint4*)(g_vbw + ((size_t)bh * 256 + tid) * 16);
        unsigned* vd = Vsh + tid * 20;
#pragma unroll
        for (int u = 0; u < 4; u++) {
            uint4 t = vs[u];
            vd[4 * u] = t.x; vd[4 * u + 1] = t.y; vd[4 * u + 2] = t.z; vd[4 * u + 3] = t.w;
        }
        float2 p = ((const float2*)(g_p + b * 512))[tid];
        psh2[tid] = p;
        cjs[tid] = w20 * p.x * p.x + w21 * p.y * p.y;
    }
    __syncthreads();

    int r4 = lane >> 2, tig = lane & 3;
    int mi = wid * 32;
    int i0 = mi + r4;
    const unsigned* qw = g_qbw + (size_t)bh * 256 * 16;
    unsigned qf[2][2][4];
#pragma unroll
    for (int m = 0; m < 2; m++)
#pragma unroll
        for (int ks = 0; ks < 2; ks++) {
            int ib = i0 + m * 16;
            int kw = ks * 8 + tig;
            qf[m][ks][0] = qw[ib * 16 + kw];
            qf[m][ks][1] = qw[(ib + 8) * 16 + kw];
            qf[m][ks][2] = qw[ib * 16 + kw + 4];
            qf[m][ks][3] = qw[(ib + 8) * 16 + kw + 4];
        }
    unsigned ax[2][4];
#pragma unroll
    for (int m = 0; m < 2; m++) {
        float2 pa = psh2[i0 + m * 16];
        float2 pb = psh2[i0 + m * 16 + 8];
        ax[m][0] = (tig == 0) ? pack_bf16x2(2.f * w20 * pa.x, 2.f * w21 * pa.y) : 0u;
        ax[m][1] = (tig == 0) ? pack_bf16x2(2.f * w20 * pb.x, 2.f * w21 * pb.y) : 0u;
        ax[m][2] = 0u; ax[m][3] = 0u;
    }

    float oacc[2][4][4];
#pragma unroll
    for (int m = 0; m < 2; m++)
#pragma unroll
        for (int n = 0; n < 4; n++)
#pragma unroll
            for (int e = 0; e < 4; e++) oacc[m][n][e] = 0.f;
    float lsum[4] = {0.f, 0.f, 0.f, 0.f};

    unsigned sK = smem_u32(Ksh), sV = smem_u32(Vsh);
    int lrow = lane & 7, lmat = lane >> 3;

    for (int c = 0; c < 16; c++) {
        int j0 = c * 16;
        // K B-frags: 2 x ldmatrix.x4 (rows j0+f*8.., halves 0..3 -> both k-steps)
        unsigned kr[2][4];
#pragma unroll
        for (int f = 0; f < 2; f++)
            ldm_x4(kr[f], sK + (((j0 + f * 8 + lrow) * 20 + lmat * 4) << 2));
        unsigned xb[2][2];
#pragma unroll
        for (int f = 0; f < 2; f++) {
            float2 pj = psh2[j0 + f * 8 + r4];
            xb[f][0] = (tig == 0) ? pack_bf16x2(pj.x, pj.y) : 0u;
            xb[f][1] = 0u;
        }
        float sa[2][2][4];
#pragma unroll
        for (int m = 0; m < 2; m++)
#pragma unroll
            for (int f = 0; f < 2; f++) {
#pragma unroll
                for (int e = 0; e < 4; e++) sa[m][f][e] = 0.f;
                mma_bf16(sa[m][f], qf[m][0], kr[f][0], kr[f][1]);
                mma_bf16(sa[m][f], qf[m][1], kr[f][2], kr[f][3]);
                mma_bf16(sa[m][f], ax[m], xb[f][0], xb[f][1]);
            }
        unsigned pA[2][4];
#pragma unroll
        for (int m = 0; m < 2; m++)
#pragma unroll
            for (int f = 0; f < 2; f++) {
                int jj = j0 + f * 8 + tig * 2;
                float cj0 = cjs[jj], cj1 = cjs[jj + 1];
                float e0 = __expf(sa[m][f][0] - cj0);
                float e1 = __expf(sa[m][f][1] - cj1);
                float e2 = __expf(sa[m][f][2] - cj0);
                float e3 = __expf(sa[m][f][3] - cj1);
                lsum[m * 2 + 0] += e0 + e1;
                lsum[m * 2 + 1] += e2 + e3;
                pA[m][f * 2 + 0] = pack_bf16x2(e0, e1);
                pA[m][f * 2 + 1] = pack_bf16x2(e2, e3);
            }
        // V B-frags: 2 x ldmatrix.x4.trans (covers d 0..31 for this k-chunk)
        unsigned vr[2][4];
#pragma unroll
        for (int g2 = 0; g2 < 2; g2++)
            ldm_x4t(vr[g2], sV + (((j0 + (lmat & 1) * 8 + lrow) * 20
                                   + (2 * g2 + (lmat >> 1)) * 4) << 2));
#pragma unroll
        for (int n2 = 0; n2 < 4; n2++) {
            unsigned vb0 = vr[n2 >> 1][(n2 & 1) * 2];
            unsigned vb1 = vr[n2 >> 1][(n2 & 1) * 2 + 1];
            mma_bf16(oacc[0][n2], pA[0], vb0, vb1);
            mma_bf16(oacc[1][n2], pA[1], vb0, vb1);
        }
    }

#pragma unroll
    for (int r = 0; r < 4; r++) {
        lsum[r] += __shfl_xor_sync(0xffffffffu, lsum[r], 1);
        lsum[r] += __shfl_xor_sync(0xffffffffu, lsum[r], 2);
    }
    float linv[4];
#pragma unroll
    for (int r = 0; r < 4; r++) linv[r] = 1.f / lsum[r];

    unsigned* og = g_attb + (size_t)b * 256 * 128;
#pragma unroll
    for (int m = 0; m < 2; m++) {
        int row = mi + m * 16 + r4;
#pragma unroll
        for (int n2 = 0; n2 < 4; n2++) {
            unsigned v0 = pack_bf16x2(oacc[m][n2][0] * linv[m * 2],
                                      oacc[m][n2][1] * linv[m * 2]);
            unsigned v1 = pack_bf16x2(oacc[m][n2][2] * linv[m * 2 + 1],
                                      oacc[m][n2][3] * linv[m * 2 + 1]);
            og[row * 128 + h * 16 + n2 * 4 + tig] = v0;
            og[(row + 8) * 128 + h * 16 + n2 * 4 + tig] = v1;
        }
    }
}

// ---------------- fused epilogue: HMMA out-proj + unsort + LN2 + FFN ----------------
__global__ void __launch_bounds__(256) epi_kernel(
    const float* __restrict__ x, const float* __restrict__ bout,
    const float* __restrict__ g2, const float* __restrict__ be2,
    const float* __restrict__ fw1, const float* __restrict__ fb1,
    const float* __restrict__ fw2, const float* __restrict__ fb2,
    float* __restrict__ out) {
    __shared__ __align__(16) float ybuf[256 * 33];      // woutsh (bf16) then ysh (fp32)
    __shared__ __align__(16) float w1sh[DD * DD];
    __shared__ __align__(16) float w2sh[DD * DD];
    int tid = threadIdx.x, wid = tid >> 5, lane = tid & 31;
    int b = blockIdx.x;

    ((float4*)w1sh)[tid] = ((const float4*)fw1)[tid];
    ((float4*)w2sh)[tid] = ((const float4*)fw2)[tid];
    unsigned* woutu = (unsigned*)ybuf;   // [32][132] pitch
    {
        int idx = tid;
#pragma unroll
        for (int u = 0; u < 16; u++) {
            int o = idx >> 7, c = idx & 127;
            woutu[o * 132 + c] = g_woutb[idx];
            idx += 256;
        }
    }
    __syncthreads();

    // HMMA: y[256 x 32] = att[256 x 256] @ wout^T
    int r4 = lane >> 2, tig = lane & 3;
    int mi = wid * 32;
    unsigned wbase = smem_u32(woutu);
    int lrow = lane & 7, lmat = lane >> 3;
    const unsigned* ag = g_attb + (size_t)b * 256 * 128;

    float yacc[2][4][4];
#pragma unroll
    for (int m = 0; m < 2; m++)
#pragma unroll
        for (int n = 0; n < 4; n++)
#pragma unroll
            for (int e = 0; e < 4; e++) yacc[m][n][e] = 0.f;

    for (int sp = 0; sp < 8; sp++) {
        unsigned br[4][4];
#pragma unroll
        for (int n0i = 0; n0i < 4; n0i++)
            ldm_x4(br[n0i], wbase + (((n0i * 8 + lrow) * 132 + (4 * sp + lmat) * 4) << 2));
        unsigned af0[2][4], af1[2][4];
#pragma unroll
        for (int m = 0; m < 2; m++) {
            int rw = mi + m * 16 + r4;
            const unsigned* arow = ag + rw * 128 + sp * 16 + tig;
            const unsigned* arow8 = ag + (rw + 8) * 128 + sp * 16 + tig;
            af0[m][0] = arow[0];  af0[m][1] = arow8[0];
            af0[m][2] = arow[4];  af0[m][3] = arow8[4];
            af1[m][0] = arow[8];  af1[m][1] = arow8[8];
            af1[m][2] = arow[12]; af1[m][3] = arow8[12];
        }
#pragma unroll
        for (int m = 0; m < 2; m++)
#pragma unroll
            for (int n0i = 0; n0i < 4; n0i++) {
                mma_bf16(yacc[m][n0i], af0[m], br[n0i][0], br[n0i][1]);
                mma_bf16(yacc[m][n0i], af1[m], br[n0i][2], br[n0i][3]);
            }
    }
    __syncthreads();   // done reading woutu; reuse as ysh
#pragma unroll
    for (int m = 0; m < 2; m++) {
        int rw = mi + m * 16 + r4;
#pragma unroll
        for (int n0i = 0; n0i < 4; n0i++) {
            int col = n0i * 8 + 2 * tig;
            ybuf[rw * 33 + col]           = yacc[m][n0i][0];
            ybuf[rw * 33 + col + 1]       = yacc[m][n0i][1];
            ybuf[(rw + 8) * 33 + col]     = yacc[m][n0i][2];
            ybuf[(rw + 8) * 33 + col + 1] = yacc[m][n0i][3];
        }
    }
    __syncthreads();

    // per-token: residual + LN2 + FFN + residual, scatter by orig
    int s = b * 256 + tid;
    int orig = (int)(g_sort[s] & 0xffffffffULL);
    float x2[32];
    const float4* xp = (const float4*)(x + orig * 32);
#pragma unroll
    for (int q8 = 0; q8 < 8; q8++) {
        float4 t = xp[q8];
        x2[4 * q8]     = t.x + ybuf[tid * 33 + 4 * q8]     + bout[4 * q8];
        x2[4 * q8 + 1] = t.y + ybuf[tid * 33 + 4 * q8 + 1] + bout[4 * q8 + 1];
        x2[4 * q8 + 2] = t.z + ybuf[tid * 33 + 4 * q8 + 2] + bout[4 * q8 + 2];
        x2[4 * q8 + 3] = t.w + ybuf[tid * 33 + 4 * q8 + 3] + bout[4 * q8 + 3];
    }

    float mu = 0.f;
#pragma unroll
    for (int d = 0; d < 32; d++) mu += x2[d];
    mu *= (1.f / 32.f);
    float var = 0.f;
#pragma unroll
    for (int d = 0; d < 32; d++) { float c = x2[d] - mu; var = fmaf(c, c, var); }
    var *= (1.f / 32.f);
    float inv = rsqrtf(var + 1e-5f);
    float ln[32];
#pragma unroll
    for (int d = 0; d < 32; d++) ln[d] = (x2[d] - mu) * inv * g2[d] + be2[d];

    float h1[32];
#pragma unroll
    for (int o = 0; o < 32; o++) {
        const float4* wr4 = (const float4*)(w1sh + o * 32);
        float acc = fb1[o];
#pragma unroll
        for (int q8 = 0; q8 < 8; q8++) {
            float4 w4 = wr4[q8];
            acc = fmaf(ln[4 * q8], w4.x, acc);
            acc = fmaf(ln[4 * q8 + 1], w4.y, acc);
            acc = fmaf(ln[4 * q8 + 2], w4.z, acc);
            acc = fmaf(ln[4 * q8 + 3], w4.w, acc);
        }
        h1[o] = fmaxf(acc, 0.f);
    }
    float res[32];
#pragma unroll
    for (int o = 0; o < 32; o++) {
        const float4* wr4 = (const float4*)(w2sh + o * 32);
        float acc = fb2[o];
#pragma unroll
        for (int q8 = 0; q8 < 8; q8++) {
            float4 w4 = wr4[q8];
            acc = fmaf(h1[4 * q8], w4.x, acc);
            acc = fmaf(h1[4 * q8 + 1], w4.y, acc);
            acc = fmaf(h1[4 * q8 + 2], w4.z, acc);
            acc = fmaf(h1[4 * q8 + 3], w4.w, acc);
        }
        res[o] = x2[o] + acc;
    }
    float4* op = (float4*)(out + orig * 32);
#pragma unroll
    for (int q8 = 0; q8 < 8; q8++)
        op[q8] = make_float4(res[4 * q8], res[4 * q8 + 1], res[4 * q8 + 2], res[4 * q8 + 3]);
}

// ---------------- host launcher ----------------
extern "C" void kernel_launch(void* const* d_in, const int* in_sizes, int n_in,
                              void* d_out, int out_size) {
    const float* x      = (const float*)d_in[0];
    const float* coords = (const float*)d_in[1];
    const float* wq     = (const float*)d_in[2];
    const float* wk     = (const float*)d_in[3];
    const float* wv     = (const float*)d_in[4];
    const float* wrpe   = (const float*)d_in[5];
    const float* wout   = (const float*)d_in[6];
    const float* bout   = (const float*)d_in[7];
    const float* g1     = (const float*)d_in[8];
    const float* be1    = (const float*)d_in[9];
    const float* g2     = (const float*)d_in[10];
    const float* be2    = (const float*)d_in[11];
    const float* fw1    = (const float*)d_in[12];
    const float* fb1    = (const float*)d_in[13];
    const float* fw2    = (const float*)d_in[14];
    const float* fb2    = (const float*)d_in[15];
    float* out = (float*)d_out;

    sort_init_local<<<32, 1024>>>(coords);
    sort_gmulti<1, 11><<<128, 256>>>(4096);   sort_lfinish<<<32, 1024>>>(4096);
    sort_gmulti<2, 11><<<64, 256>>>(8192);    sort_lfinish<<<32, 1024>>>(8192);
    sort_gmulti<3, 11><<<32, 256>>>(16384);   sort_lfinish<<<32, 1024>>>(16384);
    sort_gmulti<4, 11><<<16, 256>>>(32768);   sort_lfinish<<<32, 1024>>>(32768);
    sort_gmulti<4, 12><<<16, 256>>>(65536);
    sort_gmulti<1, 11><<<128, 256>>>(65536);  sort_lfinish<<<32, 1024>>>(65536);

    prep_kernel<<<16, 1024>>>(wq, wk, wv, wout, wrpe);
    proj_kernel<<<NBLK, 256>>>(x, coords, g1, be1);
    attn_hmma_kernel<<<NBLK * NH, 256>>>();
    epi_kernel<<<NBLK, 256>>>(x, bout, g2, be2, fw1, fb1, fw2, fb2, out);
}

// round 5
// speedup vs baseline: 6.9573x; 1.1503x over previous
#include <cuda_runtime.h>
#include <cuda_bf16.h>
#include <math.h>
#include <stdint.h>

#define N_TOK 65536
#define DD 32
#define NH 8
#define HDIM 256
#define BLK 256
#define NBLK 256

// ---------------- device scratch ----------------
__device__ unsigned long long g_sort[N_TOK];               // (key<<32)|idx, sorted
__device__ unsigned long long g_sort2[N_TOK];              // scattered (bucket-grouped)
__device__ unsigned g_histc[64 * 2048];                    // per-CTA histograms
__device__ unsigned g_bstart[2049];                        // bucket starts
__device__ unsigned g_cursor[2048];                        // scatter cursors
__device__ __align__(16) unsigned g_qbw[N_TOK * 128];      // bf16x2 [bh][i][16], q pre-scaled
__device__ __align__(16) unsigned g_kbw[N_TOK * 128];      // bf16x2 [bh][i][16]
__device__ __align__(16) unsigned g_vbw[N_TOK * 128];      // bf16x2 [bh][i][16] (token-major)
__device__ __align__(16) unsigned g_attb[N_TOK * 128];     // bf16x2 [b][i][128] token-major
__device__ float g_p[N_TOK * 2];
__device__ float g_w2[16];
__device__ __align__(16) unsigned g_wqkvb[3 * 256 * 16];   // bf16x2 weights [w][o][16]
__device__ __align__(16) unsigned g_woutb[32 * 128];       // bf16x2 [o][128]

// ---------------- helpers ----------------
__device__ __forceinline__ unsigned pack_bf16x2(float lo, float hi) {
    unsigned r;
    asm("cvt.rn.bf16x2.f32 %0, %1, %2;" : "=r"(r) : "f"(hi), "f"(lo));
    return r;
}
__device__ __forceinline__ unsigned smem_u32(const void* p) {
    unsigned a;
    asm("{ .reg .u64 t; cvta.to.shared.u64 t, %1; cvt.u32.u64 %0, t; }" : "=r"(a) : "l"(p));
    return a;
}
__device__ __forceinline__ void mma_bf16(float c[4], const unsigned a[4],
                                         unsigned b0, unsigned b1) {
    asm volatile("mma.sync.aligned.m16n8k16.row.col.f32.bf16.bf16.f32 "
                 "{%0,%1,%2,%3}, {%4,%5,%6,%7}, {%8,%9}, {%0,%1,%2,%3};"
                 : "+f"(c[0]), "+f"(c[1]), "+f"(c[2]), "+f"(c[3])
                 : "r"(a[0]), "r"(a[1]), "r"(a[2]), "r"(a[3]), "r"(b0), "r"(b1));
}
__device__ __forceinline__ void ldm_x4(unsigned r[4], unsigned addr) {
    asm volatile("ldmatrix.sync.aligned.m8n8.x4.shared.b16 {%0,%1,%2,%3}, [%4];"
                 : "=r"(r[0]), "=r"(r[1]), "=r"(r[2]), "=r"(r[3]) : "r"(addr));
}
__device__ __forceinline__ void ldm_x4t(unsigned r[4], unsigned addr) {
    asm volatile("ldmatrix.sync.aligned.m8n8.x4.trans.shared.b16 {%0,%1,%2,%3}, [%4];"
                 : "=r"(r[0]), "=r"(r[1]), "=r"(r[2]), "=r"(r[3]) : "r"(addr));
}

// ---------------- bucket sort (exact stable argsort for uniform keys) ----------------
// bucket = floor(v * 2048): x2048 is exponent shift (exact), monotone in v, and
// float bits order == value order for v >= 0, so bucket order == key order.
__global__ void __launch_bounds__(1024) sort_hist(const float* __restrict__ coords) {
    __shared__ unsigned hist[2048];
    int tid = threadIdx.x;
    hist[tid] = 0; hist[tid + 1024] = 0;
    __syncthreads();
    int gi = blockIdx.x * 1024 + tid;
    float v = coords[3 * gi];
    int b = (int)(v * 2048.f); if (b > 2047) b = 2047;
    atomicAdd(&hist[b], 1u);
    __syncthreads();
    g_histc[blockIdx.x * 2048 + tid] = hist[tid];
    g_histc[blockIdx.x * 2048 + tid + 1024] = hist[tid + 1024];
}

// one CTA: bucket prefix-sum + bf16 weight prep + RPE w2
__global__ void __launch_bounds__(1024) sort_prefix_prep(
    const float* __restrict__ wq, const float* __restrict__ wk,
    const float* __restrict__ wv, const float* __restrict__ wout,
    const float* __restrict__ wrpe) {
    __shared__ unsigned tots[2048];
    __shared__ unsigned wsum[32];
    int tid = threadIdx.x;
    int lane = tid & 31, wid = tid >> 5;

    // weight prep
    for (int gid = tid; gid < 16384; gid += 1024) {
        if (gid < 12288) {
            const float* src = (gid < 4096) ? wq : (gid < 8192) ? wk : wv;
            int r = gid & 4095; int o = r >> 4, c = r & 15;
            g_wqkvb[gid] = pack_bf16x2(src[o * 32 + 2 * c], src[o * 32 + 2 * c + 1]);
        } else {
            int r = gid - 12288; int o = r >> 7, c = r & 127;
            g_woutb[r] = pack_bf16x2(wout[o * 256 + 2 * c], wout[o * 256 + 2 * c + 1]);
        }
    }
    if (tid < 16) {
        int h = tid >> 1, c = tid & 1;
        float acc = 0.f;
        for (int d = 0; d < 32; d++)
            for (int w = 0; w < 8; w++) {
                float v = wrpe[(h * 32 + d) * 16 + c * 8 + w];
                acc += v * v;
            }
        g_w2[tid] = acc * (1.f / 256.f);
    }

    // bucket totals
    for (int b = tid; b < 2048; b += 1024) {
        unsigned t = 0;
        for (int c = 0; c < 64; c++) t += g_histc[c * 2048 + b];
        tots[b] = t;
    }
    __syncthreads();
    // exclusive scan over 2048 (pairwise + warp shuffles)
    unsigned ps = tots[2 * tid] + tots[2 * tid + 1];
    unsigned v = ps;
    for (int o = 1; o < 32; o <<= 1) {
        unsigned n = __shfl_up_sync(~0u, v, o);
        if (lane >= o) v += n;
    }
    if (lane == 31) wsum[wid] = v;
    __syncthreads();
    if (wid == 0) {
        unsigned w = wsum[lane];
        unsigned vv = w;
        for (int o = 1; o < 32; o <<= 1) {
            unsigned n = __shfl_up_sync(~0u, vv, o);
            if (lane >= o) vv += n;
        }
        wsum[lane] = vv - w;   // exclusive warp offsets
    }
    __syncthreads();
    unsigned excl = v - ps + wsum[wid];
    unsigned p0 = excl;
    unsigned p1 = excl + tots[2 * tid];
    g_bstart[2 * tid] = p0;     g_cursor[2 * tid] = p0;
    g_bstart[2 * tid + 1] = p1; g_cursor[2 * tid + 1] = p1;
    if (tid == 1023) g_bstart[2048] = p1 + tots[2047];
}

__global__ void __launch_bounds__(1024) sort_scatter(const float* __restrict__ coords) {
    int gi = blockIdx.x * 1024 + threadIdx.x;
    float v = coords[3 * gi];
    int b = (int)(v * 2048.f); if (b > 2047) b = 2047;
    unsigned pos = atomicAdd(&g_cursor[b], 1u);
    g_sort2[pos] = ((unsigned long long)__float_as_uint(v) << 32) | (unsigned)gi;
}

// one warp per bucket: exact rank sort by unique 64-bit key (erases atomic order)
__global__ void __launch_bounds__(1024) sort_buckets() {
    int wid = threadIdx.x >> 5, lane = threadIdx.x & 31;
    int b = blockIdx.x * 32 + wid;
    unsigned s0 = g_bstart[b], s1 = g_bstart[b + 1];
    int n = (int)(s1 - s0);
    for (int i = lane; i < n; i += 32) {
        unsigned long long key = g_sort2[s0 + i];
        int r = 0;
        for (int j = 0; j < n; j++) r += (g_sort2[s0 + j] < key) ? 1 : 0;
        g_sort[s0 + (unsigned)r] = key;
    }
}

// ---------------- LayerNorm + QKV projection via HMMA ----------------
__global__ void __launch_bounds__(256) proj_kernel(
    const float* __restrict__ x, const float* __restrict__ coords,
    const float* __restrict__ g1, const float* __restrict__ be1) {
    __shared__ __align__(16) unsigned xnsh[256 * 20];   // xn bf16x2, pitch 20 u32
    __shared__ __align__(16) unsigned wsh[256 * 20];    // weights bf16x2, pitch 20 u32
    int tid = threadIdx.x, wid = tid >> 5, lane = tid & 31;
    int b = blockIdx.x;
    int s = b * 256 + tid;
    int orig = (int)(g_sort[s] & 0xffffffffULL);

    float xv[32];
    const float4* xp = (const float4*)(x + orig * 32);
#pragma unroll
    for (int q8 = 0; q8 < 8; q8++) {
        float4 t = xp[q8];
        xv[4 * q8] = t.x; xv[4 * q8 + 1] = t.y; xv[4 * q8 + 2] = t.z; xv[4 * q8 + 3] = t.w;
    }
    float mu = 0.f;
#pragma unroll
    for (int d = 0; d < 32; d++) mu += xv[d];
    mu *= (1.f / 32.f);
    float var = 0.f;
#pragma unroll
    for (int d = 0; d < 32; d++) { float c = xv[d] - mu; var = fmaf(c, c, var); }
    var *= (1.f / 32.f);
    float inv = rsqrtf(var + 1e-5f);
#pragma unroll
    for (int d = 0; d < 32; d++) xv[d] = (xv[d] - mu) * inv * g1[d] + be1[d];

    g_p[2 * s]     = coords[3 * orig + 1];
    g_p[2 * s + 1] = coords[3 * orig + 2];

#pragma unroll
    for (int c = 0; c < 16; c++) xnsh[tid * 20 + c] = pack_bf16x2(xv[2 * c], xv[2 * c + 1]);
    __syncthreads();

    int r4 = lane >> 2, tig = lane & 3;
    int row0 = wid * 32 + r4;
    unsigned af[2][2][4];
#pragma unroll
    for (int m = 0; m < 2; m++)
#pragma unroll
        for (int ks = 0; ks < 2; ks++) {
            int rw = row0 + m * 16;
            af[m][ks][0] = xnsh[rw * 20 + ks * 8 + tig];
            af[m][ks][1] = xnsh[(rw + 8) * 20 + ks * 8 + tig];
            af[m][ks][2] = xnsh[rw * 20 + ks * 8 + tig + 4];
            af[m][ks][3] = xnsh[(rw + 8) * 20 + ks * 8 + tig + 4];
        }

    unsigned wbase = smem_u32(wsh);
    int lrow = lane & 7, lmat = lane >> 3;

    for (int w = 0; w < 3; w++) {
        if (w) __syncthreads();
#pragma unroll
        for (int c = 0; c < 16; c++) wsh[tid * 20 + c] = g_wqkvb[w * 4096 + tid * 16 + c];
        __syncthreads();

        unsigned* dst = (w == 0) ? g_qbw : (w == 1) ? g_kbw : g_vbw;
        float sc = (w == 0) ? 0.17677669529663687f : 1.f;

        for (int n0 = 0; n0 < 256; n0 += 8) {
            unsigned br[4];
            ldm_x4(br, wbase + (((n0 + lrow) * 20 + lmat * 4) << 2));
#pragma unroll
            for (int m = 0; m < 2; m++) {
                float acc[4] = {0.f, 0.f, 0.f, 0.f};
                mma_bf16(acc, af[m][0], br[0], br[1]);
                mma_bf16(acc, af[m][1], br[2], br[3]);
                int rw = row0 + m * 16;
                int h = n0 >> 5;
                size_t base = ((size_t)((b * 8 + h) * 256 + rw)) * 16 + ((n0 & 31) >> 1) + tig;
                dst[base]       = pack_bf16x2(acc[0] * sc, acc[1] * sc);
                dst[base + 128] = pack_bf16x2(acc[2] * sc, acc[3] * sc);
            }
        }
    }
}

// ---------------- HMMA block attention ----------------
__global__ void __launch_bounds__(256) attn_hmma_kernel() {
    __shared__ __align__(16) unsigned Ksh[256 * 20];
    __shared__ __align__(16) unsigned Vsh[256 * 20];
    __shared__ __align__(16) float2 psh2[256];
    __shared__ float cjs[256];

    int tid = threadIdx.x, wid = tid >> 5, lane = tid & 31;
    int bh = blockIdx.x;
    int b = bh >> 3, h = bh & 7;
    float w20 = g_w2[2 * h], w21 = g_w2[2 * h + 1];

    {
        const uint4* ks = (const uint4*)(g_kbw + ((size_t)bh * 256 + tid) * 16);
        unsigned* kd = Ksh + tid * 20;
#pragma unroll
        for (int u = 0; u < 4; u++) {
            uint4 t = ks[u];
            kd[4 * u] = t.x; kd[4 * u + 1] = t.y; kd[4 * u + 2] = t.z; kd[4 * u + 3] = t.w;
        }
        const uint4* vs = (const uint4*)(g_vbw + ((size_t)bh * 256 + tid) * 16);
        unsigned* vd = Vsh + tid * 20;
#pragma unroll
        for (int u = 0; u < 4; u++) {
            uint4 t = vs[u];
            vd[4 * u] = t.x; vd[4 * u + 1] = t.y; vd[4 * u + 2] = t.z; vd[4 * u + 3] = t.w;
        }
        float2 p = ((const float2*)(g_p + b * 512))[tid];
        psh2[tid] = p;
        cjs[tid] = w20 * p.x * p.x + w21 * p.y * p.y;
    }
    __syncthreads();

    int r4 = lane >> 2, tig = lane & 3;
    int mi = wid * 32;
    int i0 = mi + r4;
    const unsigned* qw = g_qbw + (size_t)bh * 256 * 16;
    unsigned qf[2][2][4];
#pragma unroll
    for (int m = 0; m < 2; m++)
#pragma unroll
        for (int ks = 0; ks < 2; ks++) {
            int ib = i0 + m * 16;
            int kw = ks * 8 + tig;
            qf[m][ks][0] = qw[ib * 16 + kw];
            qf[m][ks][1] = qw[(ib + 8) * 16 + kw];
            qf[m][ks][2] = qw[ib * 16 + kw + 4];
            qf[m][ks][3] = qw[(ib + 8) * 16 + kw + 4];
        }
    unsigned ax[2][4];
#pragma unroll
    for (int m = 0; m < 2; m++) {
        float2 pa = psh2[i0 + m * 16];
        float2 pb = psh2[i0 + m * 16 + 8];
        ax[m][0] = (tig == 0) ? pack_bf16x2(2.f * w20 * pa.x, 2.f * w21 * pa.y) : 0u;
        ax[m][1] = (tig == 0) ? pack_bf16x2(2.f * w20 * pb.x, 2.f * w21 * pb.y) : 0u;
        ax[m][2] = 0u; ax[m][3] = 0u;
    }

    float oacc[2][4][4];
#pragma unroll
    for (int m = 0; m < 2; m++)
#pragma unroll
        for (int n = 0; n < 4; n++)
#pragma unroll
            for (int e = 0; e < 4; e++) oacc[m][n][e] = 0.f;
    float lsum[4] = {0.f, 0.f, 0.f, 0.f};

    unsigned sK = smem_u32(Ksh), sV = smem_u32(Vsh);
    int lrow = lane & 7, lmat = lane >> 3;

    for (int c = 0; c < 16; c++) {
        int j0 = c * 16;
        unsigned kr[2][4];
#pragma unroll
        for (int f = 0; f < 2; f++)
            ldm_x4(kr[f], sK + (((j0 + f * 8 + lrow) * 20 + lmat * 4) << 2));
        unsigned xb[2][2];
#pragma unroll
        for (int f = 0; f < 2; f++) {
            float2 pj = psh2[j0 + f * 8 + r4];
            xb[f][0] = (tig == 0) ? pack_bf16x2(pj.x, pj.y) : 0u;
            xb[f][1] = 0u;
        }
        float sa[2][2][4];
#pragma unroll
        for (int m = 0; m < 2; m++)
#pragma unroll
            for (int f = 0; f < 2; f++) {
#pragma unroll
                for (int e = 0; e < 4; e++) sa[m][f][e] = 0.f;
                mma_bf16(sa[m][f], qf[m][0], kr[f][0], kr[f][1]);
                mma_bf16(sa[m][f], qf[m][1], kr[f][2], kr[f][3]);
                mma_bf16(sa[m][f], ax[m], xb[f][0], xb[f][1]);
            }
        unsigned pA[2][4];
#pragma unroll
        for (int m = 0; m < 2; m++)
#pragma unroll
            for (int f = 0; f < 2; f++) {
                int jj = j0 + f * 8 + tig * 2;
                float cj0 = cjs[jj], cj1 = cjs[jj + 1];
                float e0 = __expf(sa[m][f][0] - cj0);
                float e1 = __expf(sa[m][f][1] - cj1);
                float e2 = __expf(sa[m][f][2] - cj0);
                float e3 = __expf(sa[m][f][3] - cj1);
                lsum[m * 2 + 0] += e0 + e1;
                lsum[m * 2 + 1] += e2 + e3;
                pA[m][f * 2 + 0] = pack_bf16x2(e0, e1);
                pA[m][f * 2 + 1] = pack_bf16x2(e2, e3);
            }
        unsigned vr[2][4];
#pragma unroll
        for (int g2 = 0; g2 < 2; g2++)
            ldm_x4t(vr[g2], sV + (((j0 + (lmat & 1) * 8 + lrow) * 20
                                   + (2 * g2 + (lmat >> 1)) * 4) << 2));
#pragma unroll
        for (int n2 = 0; n2 < 4; n2++) {
            unsigned vb0 = vr[n2 >> 1][(n2 & 1) * 2];
            unsigned vb1 = vr[n2 >> 1][(n2 & 1) * 2 + 1];
            mma_bf16(oacc[0][n2], pA[0], vb0, vb1);
            mma_bf16(oacc[1][n2], pA[1], vb0, vb1);
        }
    }

#pragma unroll
    for (int r = 0; r < 4; r++) {
        lsum[r] += __shfl_xor_sync(0xffffffffu, lsum[r], 1);
        lsum[r] += __shfl_xor_sync(0xffffffffu, lsum[r], 2);
    }
    float linv[4];
#pragma unroll
    for (int r = 0; r < 4; r++) linv[r] = 1.f / lsum[r];

    unsigned* og = g_attb + (size_t)b * 256 * 128;
#pragma unroll
    for (int m = 0; m < 2; m++) {
        int row = mi + m * 16 + r4;
#pragma unroll
        for (int n2 = 0; n2 < 4; n2++) {
            unsigned v0 = pack_bf16x2(oacc[m][n2][0] * linv[m * 2],
                                      oacc[m][n2][1] * linv[m * 2]);
            unsigned v1 = pack_bf16x2(oacc[m][n2][2] * linv[m * 2 + 1],
                                      oacc[m][n2][3] * linv[m * 2 + 1]);
            og[row * 128 + h * 16 + n2 * 4 + tig] = v0;
            og[(row + 8) * 128 + h * 16 + n2 * 4 + tig] = v1;
        }
    }
}

// ---------------- fused epilogue: HMMA out-proj + unsort + LN2 + FFN ----------------
__global__ void __launch_bounds__(256) epi_kernel(
    const float* __restrict__ x, const float* __restrict__ bout,
    const float* __restrict__ g2, const float* __restrict__ be2,
    const float* __restrict__ fw1, const float* __restrict__ fb1,
    const float* __restrict__ fw2, const float* __restrict__ fb2,
    float* __restrict__ out) {
    __shared__ __align__(16) float ybuf[256 * 33];
    __shared__ __align__(16) float w1sh[DD * DD];
    __shared__ __align__(16) float w2sh[DD * DD];
    int tid = threadIdx.x, wid = tid >> 5, lane = tid & 31;
    int b = blockIdx.x;

    ((float4*)w1sh)[tid] = ((const float4*)fw1)[tid];
    ((float4*)w2sh)[tid] = ((const float4*)fw2)[tid];
    unsigned* woutu = (unsigned*)ybuf;
    {
        int idx = tid;
#pragma unroll
        for (int u = 0; u < 16; u++) {
            int o = idx >> 7, c = idx & 127;
            woutu[o * 132 + c] = g_woutb[idx];
            idx += 256;
        }
    }
    __syncthreads();

    int r4 = lane >> 2, tig = lane & 3;
    int mi = wid * 32;
    unsigned wbase = smem_u32(woutu);
    int lrow = lane & 7, lmat = lane >> 3;
    const unsigned* ag = g_attb + (size_t)b * 256 * 128;

    float yacc[2][4][4];
#pragma unroll
    for (int m = 0; m < 2; m++)
#pragma unroll
        for (int n = 0; n < 4; n++)
#pragma unroll
            for (int e = 0; e < 4; e++) yacc[m][n][e] = 0.f;

    for (int sp = 0; sp < 8; sp++) {
        unsigned br[4][4];
#pragma unroll
        for (int n0i = 0; n0i < 4; n0i++)
            ldm_x4(br[n0i], wbase + (((n0i * 8 + lrow) * 132 + (4 * sp + lmat) * 4) << 2));
        unsigned af0[2][4], af1[2][4];
#pragma unroll
        for (int m = 0; m < 2; m++) {
            int rw = mi + m * 16 + r4;
            const unsigned* arow = ag + rw * 128 + sp * 16 + tig;
            const unsigned* arow8 = ag + (rw + 8) * 128 + sp * 16 + tig;
            af0[m][0] = arow[0];  af0[m][1] = arow8[0];
            af0[m][2] = arow[4];  af0[m][3] = arow8[4];
            af1[m][0] = arow[8];  af1[m][1] = arow8[8];
            af1[m][2] = arow[12]; af1[m][3] = arow8[12];
        }
#pragma unroll
        for (int m = 0; m < 2; m++)
#pragma unroll
            for (int n0i = 0; n0i < 4; n0i++) {
                mma_bf16(yacc[m][n0i], af0[m], br[n0i][0], br[n0i][1]);
                mma_bf16(yacc[m][n0i], af1[m], br[n0i][2], br[n0i][3]);
            }
    }
    __syncthreads();
#pragma unroll
    for (int m = 0; m < 2; m++) {
        int rw = mi + m * 16 + r4;
#pragma unroll
        for (int n0i = 0; n0i < 4; n0i++) {
            int col = n0i * 8 + 2 * tig;
            ybuf[rw * 33 + col]           = yacc[m][n0i][0];
            ybuf[rw * 33 + col + 1]       = yacc[m][n0i][1];
            ybuf[(rw + 8) * 33 + col]     = yacc[m][n0i][2];
            ybuf[(rw + 8) * 33 + col + 1] = yacc[m][n0i][3];
        }
    }
    __syncthreads();

    int s = b * 256 + tid;
    int orig = (int)(g_sort[s] & 0xffffffffULL);
    float x2[32];
    const float4* xp = (const float4*)(x + orig * 32);
#pragma unroll
    for (int q8 = 0; q8 < 8; q8++) {
        float4 t = xp[q8];
        x2[4 * q8]     = t.x + ybuf[tid * 33 + 4 * q8]     + bout[4 * q8];
        x2[4 * q8 + 1] = t.y + ybuf[tid * 33 + 4 * q8 + 1] + bout[4 * q8 + 1];
        x2[4 * q8 + 2] = t.z + ybuf[tid * 33 + 4 * q8 + 2] + bout[4 * q8 + 2];
        x2[4 * q8 + 3] = t.w + ybuf[tid * 33 + 4 * q8 + 3] + bout[4 * q8 + 3];
    }

    float mu = 0.f;
#pragma unroll
    for (int d = 0; d < 32; d++) mu += x2[d];
    mu *= (1.f / 32.f);
    float var = 0.f;
#pragma unroll
    for (int d = 0; d < 32; d++) { float c = x2[d] - mu; var = fmaf(c, c, var); }
    var *= (1.f / 32.f);
    float inv = rsqrtf(var + 1e-5f);
    float ln[32];
#pragma unroll
    for (int d = 0; d < 32; d++) ln[d] = (x2[d] - mu) * inv * g2[d] + be2[d];

    float h1[32];
#pragma unroll
    for (int o = 0; o < 32; o++) {
        const float4* wr4 = (const float4*)(w1sh + o * 32);
        float acc = fb1[o];
#pragma unroll
        for (int q8 = 0; q8 < 8; q8++) {
            float4 w4 = wr4[q8];
            acc = fmaf(ln[4 * q8], w4.x, acc);
            acc = fmaf(ln[4 * q8 + 1], w4.y, acc);
            acc = fmaf(ln[4 * q8 + 2], w4.z, acc);
            acc = fmaf(ln[4 * q8 + 3], w4.w, acc);
        }
        h1[o] = fmaxf(acc, 0.f);
    }
    float res[32];
#pragma unroll
    for (int o = 0; o < 32; o++) {
        const float4* wr4 = (const float4*)(w2sh + o * 32);
        float acc = fb2[o];
#pragma unroll
        for (int q8 = 0; q8 < 8; q8++) {
            float4 w4 = wr4[q8];
            acc = fmaf(h1[4 * q8], w4.x, acc);
            acc = fmaf(h1[4 * q8 + 1], w4.y, acc);
            acc = fmaf(h1[4 * q8 + 2], w4.z, acc);
            acc = fmaf(h1[4 * q8 + 3], w4.w, acc);
        }
        res[o] = x2[o] + acc;
    }
    float4* op = (float4*)(out + orig * 32);
#pragma unroll
    for (int q8 = 0; q8 < 8; q8++)
        op[q8] = make_float4(res[4 * q8], res[4 * q8 + 1], res[4 * q8 + 2], res[4 * q8 + 3]);
}

// ---------------- host launcher ----------------
extern "C" void kernel_launch(void* const* d_in, const int* in_sizes, int n_in,
                              void* d_out, int out_size) {
    const float* x      = (const float*)d_in[0];
    const float* coords = (const float*)d_in[1];
    const float* wq     = (const float*)d_in[2];
    const float* wk     = (const float*)d_in[3];
    const float* wv     = (const float*)d_in[4];
    const float* wrpe   = (const float*)d_in[5];
    const float* wout   = (const float*)d_in[6];
    const float* bout   = (const float*)d_in[7];
    const float* g1     = (const float*)d_in[8];
    const float* be1    = (const float*)d_in[9];
    const float* g2     = (const float*)d_in[10];
    const float* be2    = (const float*)d_in[11];
    const float* fw1    = (const float*)d_in[12];
    const float* fb1    = (const float*)d_in[13];
    const float* fw2    = (const float*)d_in[14];
    const float* fb2    = (const float*)d_in[15];
    float* out = (float*)d_out;

    sort_hist<<<64, 1024>>>(coords);
    sort_prefix_prep<<<1, 1024>>>(wq, wk, wv, wout, wrpe);
    sort_scatter<<<64, 1024>>>(coords);
    sort_buckets<<<64, 1024>>>();
    proj_kernel<<<NBLK, 256>>>(x, coords, g1, be1);
    attn_hmma_kernel<<<NBLK * NH, 256>>>();
    epi_kernel<<<NBLK, 256>>>(x, bout, g2, be2, fw1, fb1, fw2, fb2, out);
}

// round 6
// speedup vs baseline: 8.7040x; 1.2511x over previous
#include <cuda_runtime.h>
#include <cuda_bf16.h>
#include <math.h>
#include <stdint.h>

#define N_TOK 65536
#define DD 32
#define NH 8
#define NBLK 256
#define L2E 1.4426950408889634f

// ---------------- device scratch ----------------
__device__ unsigned long long g_sort[N_TOK];               // (key<<32)|idx, sorted
__device__ unsigned long long g_sort2[N_TOK];              // bucket-grouped
__device__ unsigned g_histc[64 * 2048];
__device__ unsigned g_bstart[2049];
__device__ unsigned g_cursor[2048];
__device__ float g_w2[16];
__device__ __align__(16) unsigned g_wqkvb[3 * 256 * 16];   // bf16x2 [w][o][16]
__device__ __align__(16) unsigned g_woutb[32 * 128];       // bf16x2 [o][128]

// ---------------- helpers ----------------
__device__ __forceinline__ unsigned pack_bf16x2(float lo, float hi) {
    unsigned r;
    asm("cvt.rn.bf16x2.f32 %0, %1, %2;" : "=r"(r) : "f"(hi), "f"(lo));
    return r;
}
__device__ __forceinline__ unsigned smem_u32(const void* p) {
    unsigned a;
    asm("{ .reg .u64 t; cvta.to.shared.u64 t, %1; cvt.u32.u64 %0, t; }" : "=r"(a) : "l"(p));
    return a;
}
__device__ __forceinline__ float ex2f(float x) {
    float r; asm("ex2.approx.f32 %0, %1;" : "=f"(r) : "f"(x)); return r;
}
__device__ __forceinline__ void mma_bf16(float c[4], const unsigned a[4],
                                         unsigned b0, unsigned b1) {
    asm volatile("mma.sync.aligned.m16n8k16.row.col.f32.bf16.bf16.f32 "
                 "{%0,%1,%2,%3}, {%4,%5,%6,%7}, {%8,%9}, {%0,%1,%2,%3};"
                 : "+f"(c[0]), "+f"(c[1]), "+f"(c[2]), "+f"(c[3])
                 : "r"(a[0]), "r"(a[1]), "r"(a[2]), "r"(a[3]), "r"(b0), "r"(b1));
}
__device__ __forceinline__ void ldm_x4(unsigned r[4], unsigned addr) {
    asm volatile("ldmatrix.sync.aligned.m8n8.x4.shared.b16 {%0,%1,%2,%3}, [%4];"
                 : "=r"(r[0]), "=r"(r[1]), "=r"(r[2]), "=r"(r[3]) : "r"(addr));
}
__device__ __forceinline__ void ldm_x4t(unsigned r[4], unsigned addr) {
    asm volatile("ldmatrix.sync.aligned.m8n8.x4.trans.shared.b16 {%0,%1,%2,%3}, [%4];"
                 : "=r"(r[0]), "=r"(r[1]), "=r"(r[2]), "=r"(r[3]) : "r"(addr));
}

// ---------------- bucket sort ----------------
__global__ void __launch_bounds__(1024) sort_hist(const float* __restrict__ coords) {
    __shared__ unsigned hist[2048];
    int tid = threadIdx.x;
    hist[tid] = 0; hist[tid + 1024] = 0;
    __syncthreads();
    int gi = blockIdx.x * 1024 + tid;
    float v = coords[3 * gi];
    int b = (int)(v * 2048.f); if (b > 2047) b = 2047;
    atomicAdd(&hist[b], 1u);
    __syncthreads();
    g_histc[blockIdx.x * 2048 + tid] = hist[tid];
    g_histc[blockIdx.x * 2048 + tid + 1024] = hist[tid + 1024];
}

__global__ void __launch_bounds__(1024) sort_prefix_prep(
    const float* __restrict__ wq, const float* __restrict__ wk,
    const float* __restrict__ wv, const float* __restrict__ wout,
    const float* __restrict__ wrpe) {
    __shared__ unsigned tots[2048];
    __shared__ unsigned wsum[32];
    int tid = threadIdx.x;
    int lane = tid & 31, wid = tid >> 5;

    for (int gid = tid; gid < 16384; gid += 1024) {
        if (gid < 12288) {
            const float* src = (gid < 4096) ? wq : (gid < 8192) ? wk : wv;
            int r = gid & 4095; int o = r >> 4, c = r & 15;
            g_wqkvb[gid] = pack_bf16x2(src[o * 32 + 2 * c], src[o * 32 + 2 * c + 1]);
        } else {
            int r = gid - 12288; int o = r >> 7, c = r & 127;
            g_woutb[r] = pack_bf16x2(wout[o * 256 + 2 * c], wout[o * 256 + 2 * c + 1]);
        }
    }
    if (tid < 16) {
        int h = tid >> 1, c = tid & 1;
        float acc = 0.f;
        for (int d = 0; d < 32; d++)
            for (int w = 0; w < 8; w++) {
                float v = wrpe[(h * 32 + d) * 16 + c * 8 + w];
                acc += v * v;
            }
        g_w2[tid] = acc * (1.f / 256.f);
    }

    for (int b = tid; b < 2048; b += 1024) {
        unsigned t = 0;
        for (int c = 0; c < 64; c++) t += g_histc[c * 2048 + b];
        tots[b] = t;
    }
    __syncthreads();
    unsigned ps = tots[2 * tid] + tots[2 * tid + 1];
    unsigned v = ps;
    for (int o = 1; o < 32; o <<= 1) {
        unsigned n = __shfl_up_sync(~0u, v, o);
        if (lane >= o) v += n;
    }
    if (lane == 31) wsum[wid] = v;
    __syncthreads();
    if (wid == 0) {
        unsigned w = wsum[lane];
        unsigned vv = w;
        for (int o = 1; o < 32; o <<= 1) {
            unsigned n = __shfl_up_sync(~0u, vv, o);
            if (lane >= o) vv += n;
        }
        wsum[lane] = vv - w;
    }
    __syncthreads();
    unsigned excl = v - ps + wsum[wid];
    unsigned p0 = excl;
    unsigned p1 = excl + tots[2 * tid];
    g_bstart[2 * tid] = p0;     g_cursor[2 * tid] = p0;
    g_bstart[2 * tid + 1] = p1; g_cursor[2 * tid + 1] = p1;
    if (tid == 1023) g_bstart[2048] = p1 + tots[2047];
}

__global__ void __launch_bounds__(1024) sort_scatter(const float* __restrict__ coords) {
    int gi = blockIdx.x * 1024 + threadIdx.x;
    float v = coords[3 * gi];
    int b = (int)(v * 2048.f); if (b > 2047) b = 2047;
    unsigned pos = atomicAdd(&g_cursor[b], 1u);
    g_sort2[pos] = ((unsigned long long)__float_as_uint(v) << 32) | (unsigned)gi;
}

__global__ void __launch_bounds__(1024) sort_buckets() {
    __shared__ unsigned long long sb[32][128];
    int wid = threadIdx.x >> 5, lane = threadIdx.x & 31;
    int b = blockIdx.x * 32 + wid;
    unsigned s0 = g_bstart[b], s1 = g_bstart[b + 1];
    int n = (int)(s1 - s0);
    if (n <= 128) {
        for (int i = lane; i < n; i += 32) sb[wid][i] = g_sort2[s0 + i];
        __syncwarp();
        for (int i = lane; i < n; i += 32) {
            unsigned long long key = sb[wid][i];
            int r = 0;
            for (int j = 0; j < n; j++) r += (sb[wid][j] < key) ? 1 : 0;
            g_sort[s0 + (unsigned)r] = key;
        }
    } else {
        for (int i = lane; i < n; i += 32) {
            unsigned long long key = g_sort2[s0 + i];
            int r = 0;
            for (int j = 0; j < n; j++) r += (g_sort2[s0 + j] < key) ? 1 : 0;
            g_sort[s0 + (unsigned)r] = key;
        }
    }
}

// ---------------- MEGA kernel: LN1 + QKV proj + attention + out-proj + LN2 + FFN ----------------
// CTA = one 256-token block. Dynamic smem layout (u32 offsets):
//   xn   [0,      5120)   256 rows x pitch 20
//   K    [5120,  10240)
//   V    [10240, 15360)
//   p    [15360, 15872)   256 x float2
//   cj   [15872, 16128)   256 x float
//   w1   [16128, 17152)   1024 f32
//   w2   [17152, 18176)   1024 f32
// ybuf (256x33 f32 = 8448 u32) reuses [0, 8448) after head loop.
__global__ void __launch_bounds__(256, 2) mega_kernel(
    const float* __restrict__ x, const float* __restrict__ coords,
    const float* __restrict__ g1, const float* __restrict__ be1,
    const float* __restrict__ bout, const float* __restrict__ g2,
    const float* __restrict__ be2,
    const float* __restrict__ fw1, const float* __restrict__ fb1,
    const float* __restrict__ fw2, const float* __restrict__ fb2,
    float* __restrict__ out) {
    extern __shared__ __align__(16) unsigned smem[];
    unsigned* xnsh = smem;
    unsigned* Ksh  = smem + 5120;
    unsigned* Vsh  = smem + 10240;
    float2*   psh2 = (float2*)(smem + 15360);
    float*    cjsh = (float*)(smem + 15872);
    float*    w1sh = (float*)(smem + 16128);
    float*    w2sh = (float*)(smem + 17152);
    float*    ybuf = (float*)smem;

    int tid = threadIdx.x, wid = tid >> 5, lane = tid & 31;
    int b = blockIdx.x;
    int s = b * 256 + tid;
    int orig = (int)(g_sort[s] & 0xffffffffULL);

    ((float4*)w1sh)[tid] = ((const float4*)fw1)[tid];
    ((float4*)w2sh)[tid] = ((const float4*)fw2)[tid];

    // ---- LN1 ----
    float xv[32];
    const float4* xp = (const float4*)(x + orig * 32);
#pragma unroll
    for (int q8 = 0; q8 < 8; q8++) {
        float4 t = xp[q8];
        xv[4 * q8] = t.x; xv[4 * q8 + 1] = t.y; xv[4 * q8 + 2] = t.z; xv[4 * q8 + 3] = t.w;
    }
    float mu = 0.f;
#pragma unroll
    for (int d = 0; d < 32; d++) mu += xv[d];
    mu *= (1.f / 32.f);
    float var = 0.f;
#pragma unroll
    for (int d = 0; d < 32; d++) { float c = xv[d] - mu; var = fmaf(c, c, var); }
    var *= (1.f / 32.f);
    float inv = rsqrtf(var + 1e-5f);
#pragma unroll
    for (int d = 0; d < 32; d++) xv[d] = (xv[d] - mu) * inv * g1[d] + be1[d];
#pragma unroll
    for (int c = 0; c < 16; c++) xnsh[tid * 20 + c] = pack_bf16x2(xv[2 * c], xv[2 * c + 1]);

    psh2[tid] = make_float2(coords[3 * orig + 1], coords[3 * orig + 2]);

    int r4 = lane >> 2, tig = lane & 3;
    int lrow = lane & 7, lmat = lane >> 3;
    int mi = wid * 32;
    int row0 = mi + r4;
    int i0 = row0;
    unsigned sK = smem_u32(Ksh), sV = smem_u32(Vsh);
    const float qsc = 0.17677669529663687f * L2E;   // 1/sqrt(32) * log2(e)

    float yacc[2][4][4];
#pragma unroll
    for (int m = 0; m < 2; m++)
#pragma unroll
        for (int n = 0; n < 4; n++)
#pragma unroll
            for (int e = 0; e < 4; e++) yacc[m][n][e] = 0.f;

    for (int h = 0; h < NH; h++) {
        float w20L = g_w2[2 * h] * L2E, w21L = g_w2[2 * h + 1] * L2E;
        __syncthreads();   // prev head done reading K/V/cj (also covers initial xn/p writes)

        {
            float2 pp = psh2[tid];
            cjsh[tid] = fmaf(w20L * pp.x, pp.x, w21L * pp.y * pp.y);
        }

        // xn A-frags (this warp's 32 rows)
        unsigned af[2][2][4];
#pragma unroll
        for (int m = 0; m < 2; m++)
#pragma unroll
            for (int ks = 0; ks < 2; ks++) {
                int rw = row0 + m * 16;
                af[m][ks][0] = xnsh[rw * 20 + ks * 8 + tig];
                af[m][ks][1] = xnsh[(rw + 8) * 20 + ks * 8 + tig];
                af[m][ks][2] = xnsh[rw * 20 + ks * 8 + tig + 4];
                af[m][ks][3] = xnsh[(rw + 8) * 20 + ks * 8 + tig + 4];
            }

        // ---- project K, V into smem; Q into registers ----
        unsigned qf[2][2][4];
#pragma unroll
        for (int n0i = 0; n0i < 4; n0i++) {
            int wrow = (h * 32 + n0i * 8 + (lane >> 2)) * 16 + tig;
            // K
            {
                unsigned b00 = g_wqkvb[4096 + wrow], b01 = g_wqkvb[4096 + wrow + 4];
                unsigned b10 = g_wqkvb[4096 + wrow + 8], b11 = g_wqkvb[4096 + wrow + 12];
#pragma unroll
                for (int m = 0; m < 2; m++) {
                    float acc[4] = {0.f, 0.f, 0.f, 0.f};
                    mma_bf16(acc, af[m][0], b00, b01);
                    mma_bf16(acc, af[m][1], b10, b11);
                    int rw = row0 + m * 16;
                    Ksh[rw * 20 + n0i * 4 + tig]       = pack_bf16x2(acc[0], acc[1]);
                    Ksh[(rw + 8) * 20 + n0i * 4 + tig] = pack_bf16x2(acc[2], acc[3]);
                }
            }
            // V
            {
                unsigned b00 = g_wqkvb[8192 + wrow], b01 = g_wqkvb[8192 + wrow + 4];
                unsigned b10 = g_wqkvb[8192 + wrow + 8], b11 = g_wqkvb[8192 + wrow + 12];
#pragma unroll
                for (int m = 0; m < 2; m++) {
                    float acc[4] = {0.f, 0.f, 0.f, 0.f};
                    mma_bf16(acc, af[m][0], b00, b01);
                    mma_bf16(acc, af[m][1], b10, b11);
                    int rw = row0 + m * 16;
                    Vsh[rw * 20 + n0i * 4 + tig]       = pack_bf16x2(acc[0], acc[1]);
                    Vsh[(rw + 8) * 20 + n0i * 4 + tig] = pack_bf16x2(acc[2], acc[3]);
                }
            }
        }
        // Q (C-frag -> A-frag repack, scaled by qsc)
        {
            float qacc[2][4][4];
#pragma unroll
            for (int n0i = 0; n0i < 4; n0i++) {
                int wrow = (h * 32 + n0i * 8 + (lane >> 2)) * 16 + tig;
                unsigned b00 = g_wqkvb[wrow], b01 = g_wqkvb[wrow + 4];
                unsigned b10 = g_wqkvb[wrow + 8], b11 = g_wqkvb[wrow + 12];
#pragma unroll
                for (int m = 0; m < 2; m++) {
#pragma unroll
                    for (int e = 0; e < 4; e++) qacc[m][n0i][e] = 0.f;
                    mma_bf16(qacc[m][n0i], af[m][0], b00, b01);
                    mma_bf16(qacc[m][n0i], af[m][1], b10, b11);
                }
            }
#pragma unroll
            for (int m = 0; m < 2; m++)
#pragma unroll
                for (int ks = 0; ks < 2; ks++) {
                    qf[m][ks][0] = pack_bf16x2(qacc[m][2 * ks][0] * qsc, qacc[m][2 * ks][1] * qsc);
                    qf[m][ks][1] = pack_bf16x2(qacc[m][2 * ks][2] * qsc, qacc[m][2 * ks][3] * qsc);
                    qf[m][ks][2] = pack_bf16x2(qacc[m][2 * ks + 1][0] * qsc, qacc[m][2 * ks + 1][1] * qsc);
                    qf[m][ks][3] = pack_bf16x2(qacc[m][2 * ks + 1][2] * qsc, qacc[m][2 * ks + 1][3] * qsc);
                }
        }
        // RPE cross-term A-frags
        unsigned ax[2][4];
#pragma unroll
        for (int m = 0; m < 2; m++) {
            float2 pa = psh2[i0 + m * 16];
            float2 pb = psh2[i0 + m * 16 + 8];
            ax[m][0] = (tig == 0) ? pack_bf16x2(2.f * w20L * pa.x, 2.f * w21L * pa.y) : 0u;
            ax[m][1] = (tig == 0) ? pack_bf16x2(2.f * w20L * pb.x, 2.f * w21L * pb.y) : 0u;
            ax[m][2] = 0u; ax[m][3] = 0u;
        }
        __syncthreads();   // K/V/cj ready

        // ---- attention ----
        float oacc[2][4][4];
#pragma unroll
        for (int m = 0; m < 2; m++)
#pragma unroll
            for (int n = 0; n < 4; n++)
#pragma unroll
                for (int e = 0; e < 4; e++) oacc[m][n][e] = 0.f;
        float lsum[4] = {0.f, 0.f, 0.f, 0.f};

        for (int c = 0; c < 16; c++) {
            int j0 = c * 16;
            unsigned kr[2][4];
#pragma unroll
            for (int f = 0; f < 2; f++)
                ldm_x4(kr[f], sK + (((j0 + f * 8 + lrow) * 20 + lmat * 4) << 2));
            unsigned xb[2][2];
#pragma unroll
            for (int f = 0; f < 2; f++) {
                float2 pj = psh2[j0 + f * 8 + r4];
                xb[f][0] = (tig == 0) ? pack_bf16x2(pj.x, pj.y) : 0u;
                xb[f][1] = 0u;
            }
            float sa[2][2][4];
#pragma unroll
            for (int m = 0; m < 2; m++)
#pragma unroll
                for (int f = 0; f < 2; f++) {
#pragma unroll
                    for (int e = 0; e < 4; e++) sa[m][f][e] = 0.f;
                    mma_bf16(sa[m][f], qf[m][0], kr[f][0], kr[f][1]);
                    mma_bf16(sa[m][f], qf[m][1], kr[f][2], kr[f][3]);
                    mma_bf16(sa[m][f], ax[m], xb[f][0], xb[f][1]);
                }
            unsigned pA[2][4];
#pragma unroll
            for (int m = 0; m < 2; m++)
#pragma unroll
                for (int f = 0; f < 2; f++) {
                    int jj = j0 + f * 8 + tig * 2;
                    float cj0 = cjsh[jj], cj1 = cjsh[jj + 1];
                    float e0 = ex2f(sa[m][f][0] - cj0);
                    float e1 = ex2f(sa[m][f][1] - cj1);
                    float e2 = ex2f(sa[m][f][2] - cj0);
                    float e3 = ex2f(sa[m][f][3] - cj1);
                    lsum[m * 2 + 0] += e0 + e1;
                    lsum[m * 2 + 1] += e2 + e3;
                    pA[m][f * 2 + 0] = pack_bf16x2(e0, e1);
                    pA[m][f * 2 + 1] = pack_bf16x2(e2, e3);
                }
            unsigned vr[2][4];
#pragma unroll
            for (int g2i = 0; g2i < 2; g2i++)
                ldm_x4t(vr[g2i], sV + (((j0 + (lmat & 1) * 8 + lrow) * 20
                                        + (2 * g2i + (lmat >> 1)) * 4) << 2));
#pragma unroll
            for (int n2 = 0; n2 < 4; n2++) {
                unsigned vb0 = vr[n2 >> 1][(n2 & 1) * 2];
                unsigned vb1 = vr[n2 >> 1][(n2 & 1) * 2 + 1];
                mma_bf16(oacc[0][n2], pA[0], vb0, vb1);
                mma_bf16(oacc[1][n2], pA[1], vb0, vb1);
            }
        }

#pragma unroll
        for (int r = 0; r < 4; r++) {
            lsum[r] += __shfl_xor_sync(0xffffffffu, lsum[r], 1);
            lsum[r] += __shfl_xor_sync(0xffffffffu, lsum[r], 2);
        }

        // ---- out-proj accumulate: y += att_h @ wout_h^T ----
        unsigned oA[2][2][4];
#pragma unroll
        for (int m = 0; m < 2; m++) {
            float li0 = 1.f / lsum[2 * m], li1 = 1.f / lsum[2 * m + 1];
#pragma unroll
            for (int ks = 0; ks < 2; ks++) {
                oA[m][ks][0] = pack_bf16x2(oacc[m][2 * ks][0] * li0, oacc[m][2 * ks][1] * li0);
                oA[m][ks][1] = pack_bf16x2(oacc[m][2 * ks][2] * li1, oacc[m][2 * ks][3] * li1);
                oA[m][ks][2] = pack_bf16x2(oacc[m][2 * ks + 1][0] * li0, oacc[m][2 * ks + 1][1] * li0);
                oA[m][ks][3] = pack_bf16x2(oacc[m][2 * ks + 1][2] * li1, oacc[m][2 * ks + 1][3] * li1);
            }
        }
#pragma unroll
        for (int n0i = 0; n0i < 4; n0i++) {
            int wrow = (n0i * 8 + (lane >> 2)) * 128 + h * 16 + (lane & 3);
            unsigned b00 = g_woutb[wrow], b01 = g_woutb[wrow + 4];
            unsigned b10 = g_woutb[wrow + 8], b11 = g_woutb[wrow + 12];
#pragma unroll
            for (int m = 0; m < 2; m++) {
                mma_bf16(yacc[m][n0i], oA[m][0], b00, b01);
                mma_bf16(yacc[m][n0i], oA[m][1], b10, b11);
            }
        }
    }

    __syncthreads();
    // y frags -> smem (pitch 33 f32), reusing xn/K region
#pragma unroll
    for (int m = 0; m < 2; m++) {
        int rw = mi + m * 16 + r4;
#pragma unroll
        for (int n0i = 0; n0i < 4; n0i++) {
            int col = n0i * 8 + 2 * tig;
            ybuf[rw * 33 + col]           = yacc[m][n0i][0];
            ybuf[rw * 33 + col + 1]       = yacc[m][n0i][1];
            ybuf[(rw + 8) * 33 + col]     = yacc[m][n0i][2];
            ybuf[(rw + 8) * 33 + col + 1] = yacc[m][n0i][3];
        }
    }
    __syncthreads();

    // ---- per-token: residual + LN2 + FFN + residual, scatter ----
    float x2[32];
#pragma unroll
    for (int q8 = 0; q8 < 8; q8++) {
        float4 t = xp[q8];
        x2[4 * q8]     = t.x + ybuf[tid * 33 + 4 * q8]     + bout[4 * q8];
        x2[4 * q8 + 1] = t.y + ybuf[tid * 33 + 4 * q8 + 1] + bout[4 * q8 + 1];
        x2[4 * q8 + 2] = t.z + ybuf[tid * 33 + 4 * q8 + 2] + bout[4 * q8 + 2];
        x2[4 * q8 + 3] = t.w + ybuf[tid * 33 + 4 * q8 + 3] + bout[4 * q8 + 3];
    }
    float mu2 = 0.f;
#pragma unroll
    for (int d = 0; d < 32; d++) mu2 += x2[d];
    mu2 *= (1.f / 32.f);
    float var2 = 0.f;
#pragma unroll
    for (int d = 0; d < 32; d++) { float c = x2[d] - mu2; var2 = fmaf(c, c, var2); }
    var2 *= (1.f / 32.f);
    float inv2 = rsqrtf(var2 + 1e-5f);
    float ln[32];
#pragma unroll
    for (int d = 0; d < 32; d++) ln[d] = (x2[d] - mu2) * inv2 * g2[d] + be2[d];

    float h1[32];
#pragma unroll
    for (int o = 0; o < 32; o++) {
        const float4* wr4 = (const float4*)(w1sh + o * 32);
        float acc = fb1[o];
#pragma unroll
        for (int q8 = 0; q8 < 8; q8++) {
            float4 w4 = wr4[q8];
            acc = fmaf(ln[4 * q8], w4.x, acc);
            acc = fmaf(ln[4 * q8 + 1], w4.y, acc);
            acc = fmaf(ln[4 * q8 + 2], w4.z, acc);
            acc = fmaf(ln[4 * q8 + 3], w4.w, acc);
        }
        h1[o] = fmaxf(acc, 0.f);
    }
    float res[32];
#pragma unroll
    for (int o = 0; o < 32; o++) {
        const float4* wr4 = (const float4*)(w2sh + o * 32);
        float acc = fb2[o];
#pragma unroll
        for (int q8 = 0; q8 < 8; q8++) {
            float4 w4 = wr4[q8];
            acc = fmaf(h1[4 * q8], w4.x, acc);
            acc = fmaf(h1[4 * q8 + 1], w4.y, acc);
            acc = fmaf(h1[4 * q8 + 2], w4.z, acc);
            acc = fmaf(h1[4 * q8 + 3], w4.w, acc);
        }
        res[o] = x2[o] + acc;
    }
    float4* op = (float4*)(out + orig * 32);
#pragma unroll
    for (int q8 = 0; q8 < 8; q8++)
        op[q8] = make_float4(res[4 * q8], res[4 * q8 + 1], res[4 * q8 + 2], res[4 * q8 + 3]);
}

// ---------------- host launcher ----------------
#define MEGA_SMEM (18176 * 4)

extern "C" void kernel_launch(void* const* d_in, const int* in_sizes, int n_in,
                              void* d_out, int out_size) {
    const float* x      = (const float*)d_in[0];
    const float* coords = (const float*)d_in[1];
    const float* wq     = (const float*)d_in[2];
    const float* wk     = (const float*)d_in[3];
    const float* wv     = (const float*)d_in[4];
    const float* wrpe   = (const float*)d_in[5];
    const float* wout   = (const float*)d_in[6];
    const float* bout   = (const float*)d_in[7];
    const float* g1     = (const float*)d_in[8];
    const float* be1    = (const float*)d_in[9];
    const float* g2     = (const float*)d_in[10];
    const float* be2    = (const float*)d_in[11];
    const float* fw1    = (const float*)d_in[12];
    const float* fb1    = (const float*)d_in[13];
    const float* fw2    = (const float*)d_in[14];
    const float* fb2    = (const float*)d_in[15];
    float* out = (float*)d_out;

    cudaFuncSetAttribute(mega_kernel, cudaFuncAttributeMaxDynamicSharedMemorySize, MEGA_SMEM);

    sort_hist<<<64, 1024>>>(coords);
    sort_prefix_prep<<<1, 1024>>>(wq, wk, wv, wout, wrpe);
    sort_scatter<<<64, 1024>>>(coords);
    sort_buckets<<<64, 1024>>>();
    mega_kernel<<<NBLK, 256, MEGA_SMEM>>>(x, coords, g1, be1, bout, g2, be2,
                                          fw1, fb1, fw2, fb2, out);
}

// round 7
// speedup vs baseline: 8.7058x; 1.0002x over previous
#include <cuda_runtime.h>
#include <cuda_bf16.h>
#include <math.h>
#include <stdint.h>

#define N_TOK 65536
#define DD 32
#define NH 8
#define NBLK 256
#define L2E 1.4426950408889634f

// ---------------- device scratch ----------------
__device__ unsigned long long g_sort[N_TOK];               // (key<<32)|idx, sorted
__device__ unsigned long long g_sort2[N_TOK];              // bucket-grouped
__device__ unsigned g_histc[64 * 2048];
__device__ unsigned g_bstart[2049];
__device__ unsigned g_cursor[2048];
__device__ float g_w2[16];
__device__ __align__(16) unsigned g_wqkvb[3 * 256 * 16];   // bf16x2 [w][o][16]
__device__ __align__(16) unsigned g_woutb[32 * 128];       // bf16x2 [o][128]
__device__ __align__(16) unsigned g_xnb[N_TOK * 16];       // bf16x2 xn, sorted token-major
__device__ __align__(16) unsigned g_attb[N_TOK * 128];     // bf16x2 [b][i][128] token-major
__device__ float g_p[N_TOK * 2];

// ---------------- helpers ----------------
__device__ __forceinline__ unsigned pack_bf16x2(float lo, float hi) {
    unsigned r;
    asm("cvt.rn.bf16x2.f32 %0, %1, %2;" : "=r"(r) : "f"(hi), "f"(lo));
    return r;
}
__device__ __forceinline__ unsigned smem_u32(const void* p) {
    unsigned a;
    asm("{ .reg .u64 t; cvta.to.shared.u64 t, %1; cvt.u32.u64 %0, t; }" : "=r"(a) : "l"(p));
    return a;
}
__device__ __forceinline__ float ex2f(float x) {
    float r; asm("ex2.approx.f32 %0, %1;" : "=f"(r) : "f"(x)); return r;
}
__device__ __forceinline__ void mma_bf16(float c[4], const unsigned a[4],
                                         unsigned b0, unsigned b1) {
    asm volatile("mma.sync.aligned.m16n8k16.row.col.f32.bf16.bf16.f32 "
                 "{%0,%1,%2,%3}, {%4,%5,%6,%7}, {%8,%9}, {%0,%1,%2,%3};"
                 : "+f"(c[0]), "+f"(c[1]), "+f"(c[2]), "+f"(c[3])
                 : "r"(a[0]), "r"(a[1]), "r"(a[2]), "r"(a[3]), "r"(b0), "r"(b1));
}
__device__ __forceinline__ void ldm_x4(unsigned r[4], unsigned addr) {
    asm volatile("ldmatrix.sync.aligned.m8n8.x4.shared.b16 {%0,%1,%2,%3}, [%4];"
                 : "=r"(r[0]), "=r"(r[1]), "=r"(r[2]), "=r"(r[3]) : "r"(addr));
}
__device__ __forceinline__ void ldm_x4t(unsigned r[4], unsigned addr) {
    asm volatile("ldmatrix.sync.aligned.m8n8.x4.trans.shared.b16 {%0,%1,%2,%3}, [%4];"
                 : "=r"(r[0]), "=r"(r[1]), "=r"(r[2]), "=r"(r[3]) : "r"(addr));
}

// ---------------- bucket sort ----------------
__global__ void __launch_bounds__(1024) sort_hist(const float* __restrict__ coords) {
    __shared__ unsigned hist[2048];
    int tid = threadIdx.x;
    hist[tid] = 0; hist[tid + 1024] = 0;
    __syncthreads();
    int gi = blockIdx.x * 1024 + tid;
    float v = coords[3 * gi];
    int b = (int)(v * 2048.f); if (b > 2047) b = 2047;
    atomicAdd(&hist[b], 1u);
    __syncthreads();
    g_histc[blockIdx.x * 2048 + tid] = hist[tid];
    g_histc[blockIdx.x * 2048 + tid + 1024] = hist[tid + 1024];
}

__global__ void __launch_bounds__(1024) sort_prefix_prep(
    const float* __restrict__ wq, const float* __restrict__ wk,
    const float* __restrict__ wv, const float* __restrict__ wout,
    const float* __restrict__ wrpe) {
    __shared__ unsigned tots[2048];
    __shared__ unsigned wsum[32];
    int tid = threadIdx.x;
    int lane = tid & 31, wid = tid >> 5;

    for (int gid = tid; gid < 16384; gid += 1024) {
        if (gid < 12288) {
            const float* src = (gid < 4096) ? wq : (gid < 8192) ? wk : wv;
            int r = gid & 4095; int o = r >> 4, c = r & 15;
            g_wqkvb[gid] = pack_bf16x2(src[o * 32 + 2 * c], src[o * 32 + 2 * c + 1]);
        } else {
            int r = gid - 12288; int o = r >> 7, c = r & 127;
            g_woutb[r] = pack_bf16x2(wout[o * 256 + 2 * c], wout[o * 256 + 2 * c + 1]);
        }
    }
    if (tid < 16) {
        int h = tid >> 1, c = tid & 1;
        float acc = 0.f;
        for (int d = 0; d < 32; d++)
            for (int w = 0; w < 8; w++) {
                float v = wrpe[(h * 32 + d) * 16 + c * 8 + w];
                acc += v * v;
            }
        g_w2[tid] = acc * (1.f / 256.f);
    }

    for (int b = tid; b < 2048; b += 1024) {
        unsigned t = 0;
        for (int c = 0; c < 64; c++) t += g_histc[c * 2048 + b];
        tots[b] = t;
    }
    __syncthreads();
    unsigned ps = tots[2 * tid] + tots[2 * tid + 1];
    unsigned v = ps;
    for (int o = 1; o < 32; o <<= 1) {
        unsigned n = __shfl_up_sync(~0u, v, o);
        if (lane >= o) v += n;
    }
    if (lane == 31) wsum[wid] = v;
    __syncthreads();
    if (wid == 0) {
        unsigned w = wsum[lane];
        unsigned vv = w;
        for (int o = 1; o < 32; o <<= 1) {
            unsigned n = __shfl_up_sync(~0u, vv, o);
            if (lane >= o) vv += n;
        }
        wsum[lane] = vv - w;
    }
    __syncthreads();
    unsigned excl = v - ps + wsum[wid];
    unsigned p0 = excl;
    unsigned p1 = excl + tots[2 * tid];
    g_bstart[2 * tid] = p0;     g_cursor[2 * tid] = p0;
    g_bstart[2 * tid + 1] = p1; g_cursor[2 * tid + 1] = p1;
    if (tid == 1023) g_bstart[2048] = p1 + tots[2047];
}

__global__ void __launch_bounds__(1024) sort_scatter(const float* __restrict__ coords) {
    int gi = blockIdx.x * 1024 + threadIdx.x;
    float v = coords[3 * gi];
    int b = (int)(v * 2048.f); if (b > 2047) b = 2047;
    unsigned pos = atomicAdd(&g_cursor[b], 1u);
    g_sort2[pos] = ((unsigned long long)__float_as_uint(v) << 32) | (unsigned)gi;
}

__global__ void __launch_bounds__(1024) sort_buckets() {
    __shared__ unsigned long long sb[32][128];
    int wid = threadIdx.x >> 5, lane = threadIdx.x & 31;
    int b = blockIdx.x * 32 + wid;
    unsigned s0 = g_bstart[b], s1 = g_bstart[b + 1];
    int n = (int)(s1 - s0);
    if (n <= 128) {
        for (int i = lane; i < n; i += 32) sb[wid][i] = g_sort2[s0 + i];
        __syncwarp();
        for (int i = lane; i < n; i += 32) {
            unsigned long long key = sb[wid][i];
            int r = 0;
            for (int j = 0; j < n; j++) r += (sb[wid][j] < key) ? 1 : 0;
            g_sort[s0 + (unsigned)r] = key;
        }
    } else {
        for (int i = lane; i < n; i += 32) {
            unsigned long long key = g_sort2[s0 + i];
            int r = 0;
            for (int j = 0; j < n; j++) r += (g_sort2[s0 + j] < key) ? 1 : 0;
            g_sort[s0 + (unsigned)r] = key;
        }
    }
}

// ---------------- A: LN1 -> xn bf16 (sorted token-major) + coords ----------------
__global__ void __launch_bounds__(256) ln1_kernel(
    const float* __restrict__ x, const float* __restrict__ coords,
    const float* __restrict__ g1, const float* __restrict__ be1) {
    int tid = threadIdx.x;
    int s = blockIdx.x * 256 + tid;
    int orig = (int)(g_sort[s] & 0xffffffffULL);

    float xv[32];
    const float4* xp = (const float4*)(x + orig * 32);
#pragma unroll
    for (int q8 = 0; q8 < 8; q8++) {
        float4 t = xp[q8];
        xv[4 * q8] = t.x; xv[4 * q8 + 1] = t.y; xv[4 * q8 + 2] = t.z; xv[4 * q8 + 3] = t.w;
    }
    float mu = 0.f;
#pragma unroll
    for (int d = 0; d < 32; d++) mu += xv[d];
    mu *= (1.f / 32.f);
    float var = 0.f;
#pragma unroll
    for (int d = 0; d < 32; d++) { float c = xv[d] - mu; var = fmaf(c, c, var); }
    var *= (1.f / 32.f);
    float inv = rsqrtf(var + 1e-5f);
#pragma unroll
    for (int d = 0; d < 32; d++) xv[d] = (xv[d] - mu) * inv * g1[d] + be1[d];

    unsigned* dst = g_xnb + (size_t)s * 16;
#pragma unroll
    for (int u = 0; u < 4; u++) {
        uint4 t;
        t.x = pack_bf16x2(xv[8 * u + 0], xv[8 * u + 1]);
        t.y = pack_bf16x2(xv[8 * u + 2], xv[8 * u + 3]);
        t.z = pack_bf16x2(xv[8 * u + 4], xv[8 * u + 5]);
        t.w = pack_bf16x2(xv[8 * u + 6], xv[8 * u + 7]);
        ((uint4*)dst)[u] = t;
    }
    g_p[2 * s]     = coords[3 * orig + 1];
    g_p[2 * s + 1] = coords[3 * orig + 2];
}

// ---------------- B: per (block, head): in-CTA QKV proj + attention ----------------
// smem (u32): xn [0,5120) K [5120,10240) V [10240,15360) p [15360,15872) cj [15872,16128)
__global__ void __launch_bounds__(256) attn_kernel() {
    extern __shared__ __align__(16) unsigned smem[];
    unsigned* xnsh = smem;
    unsigned* Ksh  = smem + 5120;
    unsigned* Vsh  = smem + 10240;
    float2*   psh2 = (float2*)(smem + 15360);
    float*    cjsh = (float*)(smem + 15872);

    int tid = threadIdx.x, wid = tid >> 5, lane = tid & 31;
    int bh = blockIdx.x;
    int b = bh >> 3, h = bh & 7;
    float w20L = g_w2[2 * h] * L2E, w21L = g_w2[2 * h + 1] * L2E;

    // xn tile + coords
    {
        const uint4* src = (const uint4*)(g_xnb + (size_t)(b * 256 + tid) * 16);
        unsigned* d = xnsh + tid * 20;
#pragma unroll
        for (int u = 0; u < 4; u++) {
            uint4 t = src[u];
            d[4 * u] = t.x; d[4 * u + 1] = t.y; d[4 * u + 2] = t.z; d[4 * u + 3] = t.w;
        }
        float2 pp = ((const float2*)(g_p + b * 512))[tid];
        psh2[tid] = pp;
        cjsh[tid] = fmaf(w20L * pp.x, pp.x, w21L * pp.y * pp.y);
    }
    __syncthreads();

    int r4 = lane >> 2, tig = lane & 3;
    int lrow = lane & 7, lmat = lane >> 3;
    int mi = wid * 32;
    int row0 = mi + r4;
    unsigned sK = smem_u32(Ksh), sV = smem_u32(Vsh);
    const float qsc = 0.17677669529663687f * L2E;

    // xn A-frags
    unsigned af[2][2][4];
#pragma unroll
    for (int m = 0; m < 2; m++)
#pragma unroll
        for (int ks = 0; ks < 2; ks++) {
            int rw = row0 + m * 16;
            af[m][ks][0] = xnsh[rw * 20 + ks * 8 + tig];
            af[m][ks][1] = xnsh[(rw + 8) * 20 + ks * 8 + tig];
            af[m][ks][2] = xnsh[rw * 20 + ks * 8 + tig + 4];
            af[m][ks][3] = xnsh[(rw + 8) * 20 + ks * 8 + tig + 4];
        }

    // ---- project K, V into smem; Q into registers ----
    unsigned qf[2][2][4];
#pragma unroll
    for (int n0i = 0; n0i < 4; n0i++) {
        int wrow = (h * 32 + n0i * 8 + (lane >> 2)) * 16 + tig;
        {
            unsigned b00 = g_wqkvb[4096 + wrow], b01 = g_wqkvb[4096 + wrow + 4];
            unsigned b10 = g_wqkvb[4096 + wrow + 8], b11 = g_wqkvb[4096 + wrow + 12];
#pragma unroll
            for (int m = 0; m < 2; m++) {
                float acc[4] = {0.f, 0.f, 0.f, 0.f};
                mma_bf16(acc, af[m][0], b00, b01);
                mma_bf16(acc, af[m][1], b10, b11);
                int rw = row0 + m * 16;
                Ksh[rw * 20 + n0i * 4 + tig]       = pack_bf16x2(acc[0], acc[1]);
                Ksh[(rw + 8) * 20 + n0i * 4 + tig] = pack_bf16x2(acc[2], acc[3]);
            }
        }
        {
            unsigned b00 = g_wqkvb[8192 + wrow], b01 = g_wqkvb[8192 + wrow + 4];
            unsigned b10 = g_wqkvb[8192 + wrow + 8], b11 = g_wqkvb[8192 + wrow + 12];
#pragma unroll
            for (int m = 0; m < 2; m++) {
                float acc[4] = {0.f, 0.f, 0.f, 0.f};
                mma_bf16(acc, af[m][0], b00, b01);
                mma_bf16(acc, af[m][1], b10, b11);
                int rw = row0 + m * 16;
                Vsh[rw * 20 + n0i * 4 + tig]       = pack_bf16x2(acc[0], acc[1]);
                Vsh[(rw + 8) * 20 + n0i * 4 + tig] = pack_bf16x2(acc[2], acc[3]);
            }
        }
    }
    {
        float qacc[2][4][4];
#pragma unroll
        for (int n0i = 0; n0i < 4; n0i++) {
            int wrow = (h * 32 + n0i * 8 + (lane >> 2)) * 16 + tig;
            unsigned b00 = g_wqkvb[wrow], b01 = g_wqkvb[wrow + 4];
            unsigned b10 = g_wqkvb[wrow + 8], b11 = g_wqkvb[wrow + 12];
#pragma unroll
            for (int m = 0; m < 2; m++) {
#pragma unroll
                for (int e = 0; e < 4; e++) qacc[m][n0i][e] = 0.f;
                mma_bf16(qacc[m][n0i], af[m][0], b00, b01);
                mma_bf16(qacc[m][n0i], af[m][1], b10, b11);
            }
        }
#pragma unroll
        for (int m = 0; m < 2; m++)
#pragma unroll
            for (int ks = 0; ks < 2; ks++) {
                qf[m][ks][0] = pack_bf16x2(qacc[m][2 * ks][0] * qsc, qacc[m][2 * ks][1] * qsc);
                qf[m][ks][1] = pack_bf16x2(qacc[m][2 * ks][2] * qsc, qacc[m][2 * ks][3] * qsc);
                qf[m][ks][2] = pack_bf16x2(qacc[m][2 * ks + 1][0] * qsc, qacc[m][2 * ks + 1][1] * qsc);
                qf[m][ks][3] = pack_bf16x2(qacc[m][2 * ks + 1][2] * qsc, qacc[m][2 * ks + 1][3] * qsc);
            }
    }
    unsigned ax[2][4];
#pragma unroll
    for (int m = 0; m < 2; m++) {
        float2 pa = psh2[row0 + m * 16];
        float2 pb = psh2[row0 + m * 16 + 8];
        ax[m][0] = (tig == 0) ? pack_bf16x2(2.f * w20L * pa.x, 2.f * w21L * pa.y) : 0u;
        ax[m][1] = (tig == 0) ? pack_bf16x2(2.f * w20L * pb.x, 2.f * w21L * pb.y) : 0u;
        ax[m][2] = 0u; ax[m][3] = 0u;
    }
    __syncthreads();

    // ---- attention ----
    float oacc[2][4][4];
#pragma unroll
    for (int m = 0; m < 2; m++)
#pragma unroll
        for (int n = 0; n < 4; n++)
#pragma unroll
            for (int e = 0; e < 4; e++) oacc[m][n][e] = 0.f;
    float lsum[4] = {0.f, 0.f, 0.f, 0.f};

    for (int c = 0; c < 16; c++) {
        int j0 = c * 16;
        unsigned kr[2][4];
#pragma unroll
        for (int f = 0; f < 2; f++)
            ldm_x4(kr[f], sK + (((j0 + f * 8 + lrow) * 20 + lmat * 4) << 2));
        unsigned xb[2][2];
#pragma unroll
        for (int f = 0; f < 2; f++) {
            float2 pj = psh2[j0 + f * 8 + r4];
            xb[f][0] = (tig == 0) ? pack_bf16x2(pj.x, pj.y) : 0u;
            xb[f][1] = 0u;
        }
        float sa[2][2][4];
#pragma unroll
        for (int m = 0; m < 2; m++)
#pragma unroll
            for (int f = 0; f < 2; f++) {
#pragma unroll
                for (int e = 0; e < 4; e++) sa[m][f][e] = 0.f;
                mma_bf16(sa[m][f], qf[m][0], kr[f][0], kr[f][1]);
                mma_bf16(sa[m][f], qf[m][1], kr[f][2], kr[f][3]);
                mma_bf16(sa[m][f], ax[m], xb[f][0], xb[f][1]);
            }
        unsigned pA[2][4];
#pragma unroll
        for (int m = 0; m < 2; m++)
#pragma unroll
            for (int f = 0; f < 2; f++) {
                int jj = j0 + f * 8 + tig * 2;
                float cj0 = cjsh[jj], cj1 = cjsh[jj + 1];
                float e0 = ex2f(sa[m][f][0] - cj0);
                float e1 = ex2f(sa[m][f][1] - cj1);
                float e2 = ex2f(sa[m][f][2] - cj0);
                float e3 = ex2f(sa[m][f][3] - cj1);
                lsum[m * 2 + 0] += e0 + e1;
                lsum[m * 2 + 1] += e2 + e3;
                pA[m][f * 2 + 0] = pack_bf16x2(e0, e1);
                pA[m][f * 2 + 1] = pack_bf16x2(e2, e3);
            }
        unsigned vr[2][4];
#pragma unroll
        for (int g2i = 0; g2i < 2; g2i++)
            ldm_x4t(vr[g2i], sV + (((j0 + (lmat & 1) * 8 + lrow) * 20
                                    + (2 * g2i + (lmat >> 1)) * 4) << 2));
#pragma unroll
        for (int n2 = 0; n2 < 4; n2++) {
            unsigned vb0 = vr[n2 >> 1][(n2 & 1) * 2];
            unsigned vb1 = vr[n2 >> 1][(n2 & 1) * 2 + 1];
            mma_bf16(oacc[0][n2], pA[0], vb0, vb1);
            mma_bf16(oacc[1][n2], pA[1], vb0, vb1);
        }
    }

#pragma unroll
    for (int r = 0; r < 4; r++) {
        lsum[r] += __shfl_xor_sync(0xffffffffu, lsum[r], 1);
        lsum[r] += __shfl_xor_sync(0xffffffffu, lsum[r], 2);
    }
    float linv[4];
#pragma unroll
    for (int r = 0; r < 4; r++) linv[r] = 1.f / lsum[r];

    unsigned* og = g_attb + (size_t)b * 256 * 128;
#pragma unroll
    for (int m = 0; m < 2; m++) {
        int row = mi + m * 16 + r4;
#pragma unroll
        for (int n2 = 0; n2 < 4; n2++) {
            unsigned v0 = pack_bf16x2(oacc[m][n2][0] * linv[m * 2],
                                      oacc[m][n2][1] * linv[m * 2]);
            unsigned v1 = pack_bf16x2(oacc[m][n2][2] * linv[m * 2 + 1],
                                      oacc[m][n2][3] * linv[m * 2 + 1]);
            og[row * 128 + h * 16 + n2 * 4 + tig] = v0;
            og[(row + 8) * 128 + h * 16 + n2 * 4 + tig] = v1;
        }
    }
}

// ---------------- C: HMMA out-proj + unsort + residual + LN2 + FFN ----------------
__global__ void __launch_bounds__(256) epi_kernel(
    const float* __restrict__ x, const float* __restrict__ bout,
    const float* __restrict__ g2, const float* __restrict__ be2,
    const float* __restrict__ fw1, const float* __restrict__ fb1,
    const float* __restrict__ fw2, const float* __restrict__ fb2,
    float* __restrict__ out) {
    __shared__ __align__(16) float ybuf[256 * 33];
    __shared__ __align__(16) float w1sh[DD * DD];
    __shared__ __align__(16) float w2sh[DD * DD];
    int tid = threadIdx.x, wid = tid >> 5, lane = tid & 31;
    int b = blockIdx.x;

    ((float4*)w1sh)[tid] = ((const float4*)fw1)[tid];
    ((float4*)w2sh)[tid] = ((const float4*)fw2)[tid];
    unsigned* woutu = (unsigned*)ybuf;
    {
        int idx = tid;
#pragma unroll
        for (int u = 0; u < 16; u++) {
            int o = idx >> 7, c = idx & 127;
            woutu[o * 132 + c] = g_woutb[idx];
            idx += 256;
        }
    }
    __syncthreads();

    int r4 = lane >> 2, tig = lane & 3;
    int mi = wid * 32;
    unsigned wbase = smem_u32(woutu);
    int lrow = lane & 7, lmat = lane >> 3;
    const unsigned* ag = g_attb + (size_t)b * 256 * 128;

    float yacc[2][4][4];
#pragma unroll
    for (int m = 0; m < 2; m++)
#pragma unroll
        for (int n = 0; n < 4; n++)
#pragma unroll
            for (int e = 0; e < 4; e++) yacc[m][n][e] = 0.f;

    for (int sp = 0; sp < 8; sp++) {
        unsigned br[4][4];
#pragma unroll
        for (int n0i = 0; n0i < 4; n0i++)
            ldm_x4(br[n0i], wbase + (((n0i * 8 + lrow) * 132 + (4 * sp + lmat) * 4) << 2));
        unsigned af0[2][4], af1[2][4];
#pragma unroll
        for (int m = 0; m < 2; m++) {
            int rw = mi + m * 16 + r4;
            const unsigned* arow = ag + rw * 128 + sp * 16 + tig;
            const unsigned* arow8 = ag + (rw + 8) * 128 + sp * 16 + tig;
            af0[m][0] = arow[0];  af0[m][1] = arow8[0];
            af0[m][2] = arow[4];  af0[m][3] = arow8[4];
            af1[m][0] = arow[8];  af1[m][1] = arow8[8];
            af1[m][2] = arow[12]; af1[m][3] = arow8[12];
        }
#pragma unroll
        for (int m = 0; m < 2; m++)
#pragma unroll
            for (int n0i = 0; n0i < 4; n0i++) {
                mma_bf16(yacc[m][n0i], af0[m], br[n0i][0], br[n0i][1]);
                mma_bf16(yacc[m][n0i], af1[m], br[n0i][2], br[n0i][3]);
            }
    }
    __syncthreads();
#pragma unroll
    for (int m = 0; m < 2; m++) {
        int rw = mi + m * 16 + r4;
#pragma unroll
        for (int n0i = 0; n0i < 4; n0i++) {
            int col = n0i * 8 + 2 * tig;
            ybuf[rw * 33 + col]           = yacc[m][n0i][0];
            ybuf[rw * 33 + col + 1]       = yacc[m][n0i][1];
            ybuf[(rw + 8) * 33 + col]     = yacc[m][n0i][2];
            ybuf[(rw + 8) * 33 + col + 1] = yacc[m][n0i][3];
        }
    }
    __syncthreads();

    int s = b * 256 + tid;
    int orig = (int)(g_sort[s] & 0xffffffffULL);
    float x2[32];
    const float4* xp = (const float4*)(x + orig * 32);
#pragma unroll
    for (int q8 = 0; q8 < 8; q8++) {
        float4 t = xp[q8];
        x2[4 * q8]     = t.x + ybuf[tid * 33 + 4 * q8]     + bout[4 * q8];
        x2[4 * q8 + 1] = t.y + ybuf[tid * 33 + 4 * q8 + 1] + bout[4 * q8 + 1];
        x2[4 * q8 + 2] = t.z + ybuf[tid * 33 + 4 * q8 + 2] + bout[4 * q8 + 2];
        x2[4 * q8 + 3] = t.w + ybuf[tid * 33 + 4 * q8 + 3] + bout[4 * q8 + 3];
    }
    float mu2 = 0.f;
#pragma unroll
    for (int d = 0; d < 32; d++) mu2 += x2[d];
    mu2 *= (1.f / 32.f);
    float var2 = 0.f;
#pragma unroll
    for (int d = 0; d < 32; d++) { float c = x2[d] - mu2; var2 = fmaf(c, c, var2); }
    var2 *= (1.f / 32.f);
    float inv2 = rsqrtf(var2 + 1e-5f);
    float ln[32];
#pragma unroll
    for (int d = 0; d < 32; d++) ln[d] = (x2[d] - mu2) * inv2 * g2[d] + be2[d];

    float h1[32];
#pragma unroll
    for (int o = 0; o < 32; o++) {
        const float4* wr4 = (const float4*)(w1sh + o * 32);
        float acc = fb1[o];
#pragma unroll
        for (int q8 = 0; q8 < 8; q8++) {
            float4 w4 = wr4[q8];
            acc = fmaf(ln[4 * q8], w4.x, acc);
            acc = fmaf(ln[4 * q8 + 1], w4.y, acc);
            acc = fmaf(ln[4 * q8 + 2], w4.z, acc);
            acc = fmaf(ln[4 * q8 + 3], w4.w, acc);
        }
        h1[o] = fmaxf(acc, 0.f);
    }
    float res[32];
#pragma unroll
    for (int o = 0; o < 32; o++) {
        const float4* wr4 = (const float4*)(w2sh + o * 32);
        float acc = fb2[o];
#pragma unroll
        for (int q8 = 0; q8 < 8; q8++) {
            float4 w4 = wr4[q8];
            acc = fmaf(h1[4 * q8], w4.x, acc);
            acc = fmaf(h1[4 * q8 + 1], w4.y, acc);
            acc = fmaf(h1[4 * q8 + 2], w4.z, acc);
            acc = fmaf(h1[4 * q8 + 3], w4.w, acc);
        }
        res[o] = x2[o] + acc;
    }
    float4* op = (float4*)(out + orig * 32);
#pragma unroll
    for (int q8 = 0; q8 < 8; q8++)
        op[q8] = make_float4(res[4 * q8], res[4 * q8 + 1], res[4 * q8 + 2], res[4 * q8 + 3]);
}

// ---------------- host launcher ----------------
#define ATTN_SMEM (16128 * 4)

extern "C" void kernel_launch(void* const* d_in, const int* in_sizes, int n_in,
                              void* d_out, int out_size) {
    const float* x      = (const float*)d_in[0];
    const float* coords = (const float*)d_in[1];
    const float* wq     = (const float*)d_in[2];
    const float* wk     = (const float*)d_in[3];
    const float* wv     = (const float*)d_in[4];
    const float* wrpe   = (const float*)d_in[5];
    const float* wout   = (const float*)d_in[6];
    const float* bout   = (const float*)d_in[7];
    const float* g1     = (const float*)d_in[8];
    const float* be1    = (const float*)d_in[9];
    const float* g2     = (const float*)d_in[10];
    const float* be2    = (const float*)d_in[11];
    const float* fw1    = (const float*)d_in[12];
    const float* fb1    = (const float*)d_in[13];
    const float* fw2    = (const float*)d_in[14];
    const float* fb2    = (const float*)d_in[15];
    float* out = (float*)d_out;

    cudaFuncSetAttribute(attn_kernel, cudaFuncAttributeMaxDynamicSharedMemorySize, ATTN_SMEM);

    sort_hist<<<64, 1024>>>(coords);
    sort_prefix_prep<<<1, 1024>>>(wq, wk, wv, wout, wrpe);
    sort_scatter<<<64, 1024>>>(coords);
    sort_buckets<<<64, 1024>>>();
    ln1_kernel<<<NBLK, 256>>>(x, coords, g1, be1);
    attn_kernel<<<NBLK * NH, 256, ATTN_SMEM>>>();
    epi_kernel<<<NBLK, 256>>>(x, bout, g2, be2, fw1, fb1, fw2, fb2, out);
}